// round 14
// baseline (speedup 1.0000x reference)
#include <cuda_runtime.h>
#include <cuda_bf16.h>
#include <cuda_fp16.h>
#include <cstdint>
#include <cstddef>

#define NNODES 50000
#define NEDGES 1600000
#define FIN    128
#define HID    256
#define NCLS   40
#define CPAD   64
#define NB_SCAN 49   // ceil(50000/1024)

// ================= static device scratch =================
__device__ float g_is[NNODES];
__device__ int   g_cnt[NNODES];
__device__ int   g_fill[NNODES];
__device__ int   g_rowptr[NNODES + 1];
__device__ int   g_srcs[NEDGES];
__device__ int   g_bsum[NB_SCAN];
__device__ int   g_boff[NB_SCAN];

__device__ uint8_t g_x8[(size_t)NNODES * FIN];    // is[n]*x[n] in fp8 e4m3
__device__ uint8_t g_hs8[(size_t)NNODES * HID];   // layers 2/3 gather table, fp8 e4m3
__device__ __half  g_hs4h[(size_t)NNODES * CPAD]; // layer-4 gather table, fp16 (precision!)

__device__ __nv_bfloat16 g_t[(size_t)NNODES * FIN];    // layer-1 GEMM input (bf16)
__device__ __nv_bfloat16 g_h0[(size_t)NNODES * HID];   // activations bf16
__device__ __nv_bfloat16 g_h1[(size_t)NNODES * HID];

// weights transposed (bf16): Wt[n][k] row-major [Npad][K]
__device__ __nv_bfloat16 g_wt1[HID * FIN];
__device__ __nv_bfloat16 g_wt2[HID * HID];
__device__ __nv_bfloat16 g_wt3[HID * HID];
__device__ __nv_bfloat16 g_wt4[CPAD * HID];

// ================= PTX helpers (base compute_103-legal only) =================
__device__ __forceinline__ uint32_t smem_u32(const void* p) {
    uint32_t a;
    asm("{ .reg .u64 t; cvta.to.shared.u64 t, %1; cvt.u32.u64 %0, t; }" : "=r"(a) : "l"(p));
    return a;
}
__device__ __forceinline__ void ldsm_x4(uint32_t& r0, uint32_t& r1, uint32_t& r2, uint32_t& r3,
                                        uint32_t addr) {
    asm volatile("ldmatrix.sync.aligned.m8n8.x4.shared.b16 {%0,%1,%2,%3}, [%4];"
                 : "=r"(r0), "=r"(r1), "=r"(r2), "=r"(r3) : "r"(addr));
}
__device__ __forceinline__ void mma16816(float& c0, float& c1, float& c2, float& c3,
                                         uint32_t a0, uint32_t a1, uint32_t a2, uint32_t a3,
                                         uint32_t b0, uint32_t b1) {
    asm volatile("mma.sync.aligned.m16n8k16.row.col.f32.bf16.bf16.f32 "
                 "{%0,%1,%2,%3}, {%4,%5,%6,%7}, {%8,%9}, {%0,%1,%2,%3};"
                 : "+f"(c0), "+f"(c1), "+f"(c2), "+f"(c3)
                 : "r"(a0), "r"(a1), "r"(a2), "r"(a3), "r"(b0), "r"(b1));
}
__device__ __forceinline__ void cp_async16(uint32_t dst, const void* src, int sz) {
    asm volatile("cp.async.cg.shared.global [%0], [%1], 16, %2;"
                 :: "r"(dst), "l"(src), "r"(sz));
}
#define CP_COMMIT() asm volatile("cp.async.commit_group;")

// pack two f32 -> e4m3x2 (low byte = first value)
__device__ __forceinline__ uint16_t f32x2_to_e4m3x2(float v0, float v1) {
    uint16_t q;
    asm("cvt.rn.satfinite.e4m3x2.f32 %0, %1, %2;" : "=h"(q) : "f"(v1), "f"(v0));
    return q;
}
// accumulate 4 fp8 (one uint32) into 4 floats
__device__ __forceinline__ void acc4f8(float* a, uint32_t v) {
    uint16_t lo = (uint16_t)(v & 0xFFFFu), hi = (uint16_t)(v >> 16);
    uint32_t h0, h1;
    asm("cvt.rn.f16x2.e4m3x2 %0, %1;" : "=r"(h0) : "h"(lo));
    asm("cvt.rn.f16x2.e4m3x2 %0, %1;" : "=r"(h1) : "h"(hi));
    float2 f0 = __half22float2(*reinterpret_cast<__half2*>(&h0));
    float2 f1 = __half22float2(*reinterpret_cast<__half2*>(&h1));
    a[0] += f0.x; a[1] += f0.y; a[2] += f1.x; a[3] += f1.y;
}
__device__ __forceinline__ void acc8f8(float* a, uint2 v) {
    acc4f8(a, v.x);
    acc4f8(a + 4, v.y);
}
__device__ __forceinline__ void acc4h(float* a, uint2 v) {
    __half2* h = reinterpret_cast<__half2*>(&v);
#pragma unroll
    for (int i = 0; i < 2; i++) {
        float2 f = __half22float2(h[i]);
        a[2 * i]     += f.x;
        a[2 * i + 1] += f.y;
    }
}

// ================= graph preprocessing =================
__global__ void degree_kernel(const int* __restrict__ dst) {
    int e = blockIdx.x * blockDim.x + threadIdx.x;
    if (e < NEDGES) atomicAdd(&g_cnt[dst[e]], 1);
}
__global__ __launch_bounds__(1024) void scan_block_kernel() {   // also computes g_is
    __shared__ int ws[32];
    int t = threadIdx.x, b = blockIdx.x;
    int i = b * 1024 + t;
    int v = (i < NNODES) ? g_cnt[i] : 0;
    if (i < NNODES) g_is[i] = rsqrtf((float)v + 1.0f);
    int lane = t & 31, w = t >> 5;
    int x = v;
#pragma unroll
    for (int off = 1; off < 32; off <<= 1) {
        int y = __shfl_up_sync(0xffffffffu, x, off);
        if (lane >= off) x += y;
    }
    if (lane == 31) ws[w] = x;
    __syncthreads();
    if (w == 0) {
        int s = ws[lane];
#pragma unroll
        for (int off = 1; off < 32; off <<= 1) {
            int y = __shfl_up_sync(0xffffffffu, s, off);
            if (lane >= off) s += y;
        }
        ws[lane] = s;
    }
    __syncthreads();
    int incl = x + (w ? ws[w - 1] : 0);
    if (i < NNODES) g_rowptr[i] = incl - v;
    if (t == 1023) g_bsum[b] = incl;
}
__global__ void scan_tops_kernel() {
    __shared__ int s[64];
    int t = threadIdx.x;
    int v = (t < NB_SCAN) ? g_bsum[t] : 0;
    s[t] = v;
    __syncthreads();
    for (int off = 1; off < 64; off <<= 1) {
        int y = (t >= off) ? s[t - off] : 0;
        __syncthreads();
        s[t] += y;
        __syncthreads();
    }
    if (t < NB_SCAN) g_boff[t] = s[t] - v;
    if (t == NB_SCAN - 1) g_rowptr[NNODES] = s[t];
}
__global__ __launch_bounds__(1024) void scan_add_kernel() {
    int i = blockIdx.x * 1024 + threadIdx.x;
    if (i < NNODES) g_rowptr[i] += g_boff[blockIdx.x];
}
__global__ void fill_kernel(const int* __restrict__ src, const int* __restrict__ dst) {
    int e = blockIdx.x * blockDim.x + threadIdx.x;
    if (e < NEDGES) {
        int d = dst[e];
        int p = atomicAdd(&g_fill[d], 1);
        g_srcs[g_rowptr[d] + p] = src[e];
    }
}
// all 4 weights transposed -> bf16, one launch
#define W1E (FIN * HID)
#define W2E (HID * HID)
#define W3E (HID * HID)
#define W4E (HID * CPAD)
__global__ void wprep_all_kernel(const float* __restrict__ W1, const float* __restrict__ W2,
                                 const float* __restrict__ W3, const float* __restrict__ W4) {
    int i = blockIdx.x * blockDim.x + threadIdx.x;
    const float* W; __nv_bfloat16* dw;
    int K, Nw, j;
    if (i < W1E) { W = W1; dw = g_wt1; K = FIN; Nw = HID; j = i; }
    else if (i < W1E + W2E) { W = W2; dw = g_wt2; K = HID; Nw = HID; j = i - W1E; }
    else if (i < W1E + W2E + W3E) { W = W3; dw = g_wt3; K = HID; Nw = HID; j = i - W1E - W2E; }
    else if (i < W1E + W2E + W3E + W4E) { W = W4; dw = g_wt4; K = HID; Nw = NCLS; j = i - W1E - W2E - W3E; }
    else return;
    int n = j / K, k = j % K;
    float v = (n < Nw) ? W[k * Nw + n] : 0.0f;
    dw[j] = __float2bfloat16(v);
}
// x8[n][f] = fp8(is[n] * x[n][f])
__global__ void xprep_kernel(const float4* __restrict__ x) {
    int i = blockIdx.x * blockDim.x + threadIdx.x;   // one float4 (4 feats)
    if (i < NNODES * FIN / 4) {
        int n = i >> 5;                              // 32 float4 per node
        float isn = g_is[n];
        float4 v = x[i];
        uint16_t lo = f32x2_to_e4m3x2(isn * v.x, isn * v.y);
        uint16_t hi = f32x2_to_e4m3x2(isn * v.z, isn * v.w);
        reinterpret_cast<uint32_t*>(g_x8)[i] = (uint32_t)lo | ((uint32_t)hi << 16);
    }
}

// ================= aggregation kernels (fp8/fp16 gather, fp32 accum) =================
// layer-1: warp per node, fp8 gather; t[n] = is[n]*(sum_src x8[src] + x8[n]) -> bf16
__global__ __launch_bounds__(256) void agg_x_kernel() {
    int n = blockIdx.x * 8 + (threadIdx.x >> 5);
    int t = threadIdx.x & 31;                // 4 feats per thread
    if (n >= NNODES) return;
    const uint32_t* xr = reinterpret_cast<const uint32_t*>(g_x8);   // 32 u32 per row
    int beg = g_rowptr[n], end = g_rowptr[n + 1];
    float a[4] = {0.f, 0.f, 0.f, 0.f};
    acc4f8(a, xr[(size_t)n * 32 + t]);       // self (already is-scaled)
    int e = beg;
    for (; e + 4 <= end; e += 4) {
        int s0 = g_srcs[e], s1 = g_srcs[e + 1], s2 = g_srcs[e + 2], s3 = g_srcs[e + 3];
        uint32_t u0 = xr[(size_t)s0 * 32 + t];
        uint32_t u1 = xr[(size_t)s1 * 32 + t];
        uint32_t u2 = xr[(size_t)s2 * 32 + t];
        uint32_t u3 = xr[(size_t)s3 * 32 + t];
        acc4f8(a, u0); acc4f8(a, u1); acc4f8(a, u2); acc4f8(a, u3);
    }
    for (; e < end; e++) acc4f8(a, xr[(size_t)g_srcs[e] * 32 + t]);
    float isn = g_is[n];
    unsigned short hh[4];
#pragma unroll
    for (int k = 0; k < 4; k++) {
        __nv_bfloat16 h = __float2bfloat16(isn * a[k]);
        hh[k] = *reinterpret_cast<unsigned short*>(&h);
    }
    *(uint2*)(g_t + (size_t)n * FIN + 4 * t) = *(uint2*)hh;
}
// mid layers: warp per node, fp8 gather (8 feats = uint2); out = relu(is*sum + b) -> bf16
__global__ __launch_bounds__(256) void agg_mid_kernel(
    const float* __restrict__ bias, __nv_bfloat16* __restrict__ oh) {
    int n = blockIdx.x * 8 + (threadIdx.x >> 5);
    int t = threadIdx.x & 31;                // feats [8t, 8t+8)
    if (n >= NNODES) return;
    const uint2* hr = reinterpret_cast<const uint2*>(g_hs8);   // 32 uint2 per row
    int beg = g_rowptr[n], end = g_rowptr[n + 1];
    float a[8] = {0.f, 0.f, 0.f, 0.f, 0.f, 0.f, 0.f, 0.f};
    acc8f8(a, hr[(size_t)n * 32 + t]);       // self
    int e = beg;
    for (; e + 4 <= end; e += 4) {
        int s0 = g_srcs[e], s1 = g_srcs[e + 1], s2 = g_srcs[e + 2], s3 = g_srcs[e + 3];
        uint2 u0 = hr[(size_t)s0 * 32 + t];
        uint2 u1 = hr[(size_t)s1 * 32 + t];
        uint2 u2 = hr[(size_t)s2 * 32 + t];
        uint2 u3 = hr[(size_t)s3 * 32 + t];
        acc8f8(a, u0); acc8f8(a, u1); acc8f8(a, u2); acc8f8(a, u3);
    }
    for (; e < end; e++) acc8f8(a, hr[(size_t)g_srcs[e] * 32 + t]);
    float isn = g_is[n];
    unsigned short hh[8];
#pragma unroll
    for (int k = 0; k < 8; k++) {
        __nv_bfloat16 h = __float2bfloat16(fmaxf(isn * a[k] + bias[8 * t + k], 0.0f));
        hh[k] = *reinterpret_cast<unsigned short*>(&h);
    }
    *(uint4*)(oh + (size_t)n * HID + 8 * t) = *(uint4*)hh;
}
// layer 4: fp16 gather (precision-critical), 16 thr/node; + bias + log_softmax
__global__ __launch_bounds__(256) void agg40_lsm_kernel(
    const float* __restrict__ b4, float* __restrict__ out) {
    int n = blockIdx.x * 16 + (threadIdx.x >> 4);
    int t = threadIdx.x & 15;                // cols [4t, 4t+4)
    if (n >= NNODES) return;
    const uint2* hr = reinterpret_cast<const uint2*>(g_hs4h);
    int beg = g_rowptr[n], end = g_rowptr[n + 1];
    float a[4] = {0.f, 0.f, 0.f, 0.f};
    acc4h(a, hr[(size_t)n * 16 + t]);
    int e = beg;
    for (; e + 4 <= end; e += 4) {
        int s0 = g_srcs[e], s1 = g_srcs[e + 1], s2 = g_srcs[e + 2], s3 = g_srcs[e + 3];
        uint2 u0 = hr[(size_t)s0 * 16 + t];
        uint2 u1 = hr[(size_t)s1 * 16 + t];
        uint2 u2 = hr[(size_t)s2 * 16 + t];
        uint2 u3 = hr[(size_t)s3 * 16 + t];
        acc4h(a, u0); acc4h(a, u1); acc4h(a, u2); acc4h(a, u3);
    }
    for (; e < end; e++) acc4h(a, hr[(size_t)g_srcs[e] * 16 + t]);
    float sc = g_is[n];
    int col0 = 4 * t;
    float v[4];
#pragma unroll
    for (int k = 0; k < 4; k++)
        v[k] = (col0 + k < NCLS) ? (sc * a[k] + b4[col0 + k]) : -1e30f;
    float m = fmaxf(fmaxf(v[0], v[1]), fmaxf(v[2], v[3]));
#pragma unroll
    for (int off = 8; off; off >>= 1) m = fmaxf(m, __shfl_xor_sync(0xffffffffu, m, off));
    float se = 0.f;
#pragma unroll
    for (int k = 0; k < 4; k++) se += (col0 + k < NCLS) ? __expf(v[k] - m) : 0.f;
#pragma unroll
    for (int off = 8; off; off >>= 1) se += __shfl_xor_sync(0xffffffffu, se, off);
    float lse = m + __logf(se);
    if (t < 10) {
        float4 o;
        o.x = v[0] - lse; o.y = v[1] - lse; o.z = v[2] - lse; o.w = v[3] - lse;
        *(float4*)(out + (size_t)n * NCLS + col0) = o;
    }
}

// ================= single-bf16 HMMA GEMM, cp.async pipelined =================
// MODE 0: Ch = D*g_is[m] fp16 (layer 4); MODE 1: relu(D+bias) -> Cb bf16 (layer 1);
// MODE 2: C8 = fp8(D*g_is[m]) (layers 2/3).
#define ASTR 72

template <int KT, int BN_T, int MODE>
__global__ __launch_bounds__(256, 2) void mma_gemm_kernel(
    const __nv_bfloat16* __restrict__ A,
    const __nv_bfloat16* __restrict__ B,
    int NT,
    __half* __restrict__ Ch,
    uint8_t* __restrict__ C8,
    __nv_bfloat16* __restrict__ Cb,
    const float* __restrict__ bias)
{
    extern __shared__ __nv_bfloat16 sm[];
    constexpr int NCH = KT / 64;
    constexpr int BSTR = KT + 8;
    constexpr int ASTG_B = 128 * ASTR * 2;
    constexpr int ABUF_B = 2 * ASTG_B;

    const int tid = threadIdx.x;
    const int lane = tid & 31;
    const int wid = tid >> 5;
    const int wm = wid & 3;
    const int wn = wid >> 2;
    constexpr int WN = BN_T / 2;
    constexpr int NTILES = WN / 8;

    const int row0 = blockIdx.x * 128;
    const int col0 = blockIdx.y * BN_T;

    const uint32_t uS = smem_u32(sm);
    const uint32_t uB = uS + ABUF_B;

    auto loadA = [&](int c) {
        int k0 = c * 64;
        uint32_t ab = uS + (c & 1) * ASTG_B;
#pragma unroll
        for (int it = 0; it < 4; it++) {
            int idx = tid + it * 256;
            int r = idx >> 3, q = idx & 7;
            int gr = row0 + r;
            int sz = (gr < NNODES) ? 16 : 0;
            cp_async16(ab + (uint32_t)(r * ASTR + q * 8) * 2,
                       A + (size_t)gr * KT + k0 + q * 8, sz);
        }
    };

    {
        constexpr int BUNITS = BN_T * KT / 8;
        for (int u = tid; u < BUNITS; u += 256) {
            int n = u / (KT / 8), q = u % (KT / 8);
            cp_async16(uB + (uint32_t)(n * BSTR + q * 8) * 2,
                       B + (size_t)(col0 + n) * KT + q * 8, 16);
        }
        loadA(0);
        CP_COMMIT();
    }

    float acc[2][NTILES][4];
#pragma unroll
    for (int i = 0; i < 2; i++)
#pragma unroll
        for (int j = 0; j < NTILES; j++)
#pragma unroll
            for (int q = 0; q < 4; q++) acc[i][j][q] = 0.0f;

    const int a_r = (lane & 7) + ((lane >> 3) & 1) * 8;
    const int a_k = (lane >> 4) * 8;
    const int b_n = (lane & 7) + ((lane >> 4) & 1) * 8;
    const int b_k = ((lane >> 3) & 1) * 8;

#pragma unroll
    for (int c = 0; c < NCH; c++) {
        if (c + 1 < NCH) {
            loadA(c + 1);
            CP_COMMIT();
            asm volatile("cp.async.wait_group 1;");
        } else {
            asm volatile("cp.async.wait_group 0;");
        }
        __syncthreads();

        uint32_t ab = uS + (c & 1) * ASTG_B;
#pragma unroll
        for (int ks = 0; ks < 4; ks++) {
            uint32_t ah[2][4];
#pragma unroll
            for (int mt = 0; mt < 2; mt++) {
                uint32_t off = (uint32_t)(((wm * 32 + mt * 16 + a_r) * ASTR + ks * 16 + a_k) * 2);
                ldsm_x4(ah[mt][0], ah[mt][1], ah[mt][2], ah[mt][3], ab + off);
            }
            uint32_t bh[NTILES][2];
#pragma unroll
            for (int nb = 0; nb < NTILES / 2; nb++) {
                uint32_t off = (uint32_t)(((wn * WN + nb * 16 + b_n) * BSTR + c * 64 + ks * 16 + b_k) * 2);
                uint32_t r0, r1, r2, r3;
                ldsm_x4(r0, r1, r2, r3, uB + off);
                bh[nb * 2][0] = r0; bh[nb * 2][1] = r1;
                bh[nb * 2 + 1][0] = r2; bh[nb * 2 + 1][1] = r3;
            }
#pragma unroll
            for (int mt = 0; mt < 2; mt++)
#pragma unroll
                for (int nt = 0; nt < NTILES; nt++)
                    mma16816(acc[mt][nt][0], acc[mt][nt][1], acc[mt][nt][2], acc[mt][nt][3],
                             ah[mt][0], ah[mt][1], ah[mt][2], ah[mt][3], bh[nt][0], bh[nt][1]);
        }
        __syncthreads();
    }

    // ---- epilogue ----
    const int rbase = row0 + wm * 32 + (lane >> 2);
    const int cbase = col0 + wn * WN + ((lane & 3) * 2);
#pragma unroll
    for (int mt = 0; mt < 2; mt++) {
#pragma unroll
        for (int half = 0; half < 2; half++) {
            int gr = rbase + mt * 16 + half * 8;
            if (gr < NNODES) {
                if (MODE == 0) {
                    float s = g_is[gr];
#pragma unroll
                    for (int nt = 0; nt < NTILES; nt++) {
                        __half2 p = __floats2half2_rn(acc[mt][nt][half * 2 + 0] * s,
                                                      acc[mt][nt][half * 2 + 1] * s);
                        *(__half2*)(Ch + (size_t)gr * NT + cbase + nt * 8) = p;
                    }
                } else if (MODE == 2) {
                    float s = g_is[gr];
#pragma unroll
                    for (int nt = 0; nt < NTILES; nt++) {
                        uint16_t q = f32x2_to_e4m3x2(acc[mt][nt][half * 2 + 0] * s,
                                                     acc[mt][nt][half * 2 + 1] * s);
                        *(uint16_t*)(C8 + (size_t)gr * NT + cbase + nt * 8) = q;
                    }
                } else {
#pragma unroll
                    for (int nt = 0; nt < NTILES; nt++) {
                        int c = cbase + nt * 8;
                        float v0 = fmaxf(acc[mt][nt][half * 2 + 0] + bias[c], 0.0f);
                        float v1 = fmaxf(acc[mt][nt][half * 2 + 1] + bias[c + 1], 0.0f);
                        __nv_bfloat162 hp;
                        hp.x = __float2bfloat16(v0);
                        hp.y = __float2bfloat16(v1);
                        *(__nv_bfloat162*)(Cb + (size_t)gr * NT + c) = hp;
                    }
                }
            }
        }
    }
}

// ================= launch =================
extern "C" void kernel_launch(void* const* d_in, const int* in_sizes, int n_in,
                              void* d_out, int out_size)
{
    const float* x  = (const float*)d_in[0];
    const int*   ei = (const int*)  d_in[1];
    const float* W1 = (const float*)d_in[2];
    const float* b1 = (const float*)d_in[3];
    const float* W2 = (const float*)d_in[4];
    const float* b2 = (const float*)d_in[5];
    const float* W3 = (const float*)d_in[6];
    const float* b3 = (const float*)d_in[7];
    const float* W4 = (const float*)d_in[8];
    const float* b4 = (const float*)d_in[9];
    float* out = (float*)d_out;

    const int* src = ei;
    const int* dst = ei + NEDGES;

    __nv_bfloat16 *tptr, *h0, *h1, *wt1, *wt2, *wt3, *wt4;
    __half* hs4h;
    uint8_t* hs8;
    int *cntp, *fillp;
    cudaGetSymbolAddress((void**)&tptr, g_t);
    cudaGetSymbolAddress((void**)&h0,  g_h0);
    cudaGetSymbolAddress((void**)&h1,  g_h1);
    cudaGetSymbolAddress((void**)&wt1, g_wt1);
    cudaGetSymbolAddress((void**)&wt2, g_wt2);
    cudaGetSymbolAddress((void**)&wt3, g_wt3);
    cudaGetSymbolAddress((void**)&wt4, g_wt4);
    cudaGetSymbolAddress((void**)&hs8,  g_hs8);
    cudaGetSymbolAddress((void**)&hs4h, g_hs4h);
    cudaGetSymbolAddress((void**)&cntp, g_cnt);
    cudaGetSymbolAddress((void**)&fillp, g_fill);

    const int SMEM_L1 = 36864 + 128 * (128 + 8) * 2;  // 71680
    const int SMEM_L2 = 36864 + 128 * (256 + 8) * 2;  // 104448
    const int SMEM_L4 = 36864 + 64  * (256 + 8) * 2;  // 70656
    cudaFuncSetAttribute(mma_gemm_kernel<128, 128, 1>, cudaFuncAttributeMaxDynamicSharedMemorySize, SMEM_L1);
    cudaFuncSetAttribute(mma_gemm_kernel<256, 128, 2>, cudaFuncAttributeMaxDynamicSharedMemorySize, SMEM_L2);
    cudaFuncSetAttribute(mma_gemm_kernel<256, 64, 0>,  cudaFuncAttributeMaxDynamicSharedMemorySize, SMEM_L4);

    const int TB = 256;
    int edgeBlocks = (NEDGES + TB - 1) / TB;

    // ---- graph build ----
    cudaMemsetAsync(cntp, 0, NNODES * sizeof(int));
    cudaMemsetAsync(fillp, 0, NNODES * sizeof(int));
    degree_kernel<<<edgeBlocks, TB>>>(dst);
    scan_block_kernel<<<NB_SCAN, 1024>>>();
    scan_tops_kernel<<<1, 64>>>();
    scan_add_kernel<<<NB_SCAN, 1024>>>();
    fill_kernel<<<edgeBlocks, TB>>>(src, dst);

    // ---- weight + x prep ----
    const int WALL = W1E + W2E + W3E + W4E;
    wprep_all_kernel<<<(WALL + TB - 1) / TB, TB>>>(W1, W2, W3, W4);
    xprep_kernel<<<(NNODES * FIN / 4 + TB - 1) / TB, TB>>>((const float4*)x);

    int mBlocks = (NNODES + 127) / 128;          // 391
    dim3 gHID(mBlocks, 2);
    dim3 gC(mBlocks, 1);
    int warpNodeBlocks = (NNODES + 7) / 8;       // 6250
    int a40Blocks = (NNODES + 15) / 16;          // 3125

    // layer 1: aggregate-first (fp8 gather), GEMM fused bias+relu
    agg_x_kernel<<<warpNodeBlocks, TB>>>();
    mma_gemm_kernel<128, 128, 1><<<gHID, 256, SMEM_L1>>>(
        tptr, wt1, HID, nullptr, nullptr, h0, b1);
    // layer 2 (fp8 gather table)
    mma_gemm_kernel<256, 128, 2><<<gHID, 256, SMEM_L2>>>(
        h0, wt2, HID, nullptr, hs8, nullptr, nullptr);
    agg_mid_kernel<<<warpNodeBlocks, TB>>>(b2, h1);
    // layer 3 (fp8 gather table)
    mma_gemm_kernel<256, 128, 2><<<gHID, 256, SMEM_L2>>>(
        h1, wt3, HID, nullptr, hs8, nullptr, nullptr);
    agg_mid_kernel<<<warpNodeBlocks, TB>>>(b3, h0);
    // layer 4 (fp16 table — precision-critical) + log_softmax
    mma_gemm_kernel<256, 64, 0><<<gC, 256, SMEM_L4>>>(
        h0, wt4, CPAD, hs4h, nullptr, nullptr, nullptr);
    agg40_lsm_kernel<<<a40Blocks, TB>>>(b4, out);
}

// round 15
// speedup vs baseline: 1.1017x; 1.1017x over previous
#include <cuda_runtime.h>
#include <cuda_bf16.h>
#include <cuda_fp16.h>
#include <cstdint>
#include <cstddef>

#define NNODES 50000
#define NEDGES 1600000
#define FIN    128
#define HID    256
#define NCLS   40
#define CPAD   64
#define NB_SCAN 49   // ceil(50000/1024)

// ================= static device scratch =================
__device__ float g_is[NNODES];
__device__ int   g_cnt[NNODES];
__device__ int   g_fill[NNODES];
__device__ int   g_rowptr[NNODES + 1];
__device__ int   g_srcs[NEDGES];
__device__ int   g_bsum[NB_SCAN];
__device__ int   g_boff[NB_SCAN];

__device__ uint8_t g_x8[(size_t)NNODES * FIN];    // is[n]*x[n] in fp8 e4m3
__device__ uint8_t g_hs8[(size_t)NNODES * HID];   // layers 2/3 gather table, fp8 e4m3
__device__ __half  g_hs4h[(size_t)NNODES * CPAD]; // layer-4 gather table, fp16 (precision!)

__device__ __nv_bfloat16 g_t[(size_t)NNODES * FIN];    // layer-1 GEMM input (bf16)
__device__ __nv_bfloat16 g_h0[(size_t)NNODES * HID];   // activations bf16
__device__ __nv_bfloat16 g_h1[(size_t)NNODES * HID];

// weights transposed (bf16): Wt[n][k] row-major [Npad][K]
__device__ __nv_bfloat16 g_wt1[HID * FIN];
__device__ __nv_bfloat16 g_wt2[HID * HID];
__device__ __nv_bfloat16 g_wt3[HID * HID];
__device__ __nv_bfloat16 g_wt4[CPAD * HID];

// ================= PTX helpers (base compute_103-legal only) =================
__device__ __forceinline__ uint32_t smem_u32(const void* p) {
    uint32_t a;
    asm("{ .reg .u64 t; cvta.to.shared.u64 t, %1; cvt.u32.u64 %0, t; }" : "=r"(a) : "l"(p));
    return a;
}
__device__ __forceinline__ void ldsm_x4(uint32_t& r0, uint32_t& r1, uint32_t& r2, uint32_t& r3,
                                        uint32_t addr) {
    asm volatile("ldmatrix.sync.aligned.m8n8.x4.shared.b16 {%0,%1,%2,%3}, [%4];"
                 : "=r"(r0), "=r"(r1), "=r"(r2), "=r"(r3) : "r"(addr));
}
__device__ __forceinline__ void mma16816(float& c0, float& c1, float& c2, float& c3,
                                         uint32_t a0, uint32_t a1, uint32_t a2, uint32_t a3,
                                         uint32_t b0, uint32_t b1) {
    asm volatile("mma.sync.aligned.m16n8k16.row.col.f32.bf16.bf16.f32 "
                 "{%0,%1,%2,%3}, {%4,%5,%6,%7}, {%8,%9}, {%0,%1,%2,%3};"
                 : "+f"(c0), "+f"(c1), "+f"(c2), "+f"(c3)
                 : "r"(a0), "r"(a1), "r"(a2), "r"(a3), "r"(b0), "r"(b1));
}
__device__ __forceinline__ void cp_async16(uint32_t dst, const void* src, int sz) {
    asm volatile("cp.async.cg.shared.global [%0], [%1], 16, %2;"
                 :: "r"(dst), "l"(src), "r"(sz));
}
#define CP_COMMIT() asm volatile("cp.async.commit_group;")

// pack two f32 -> e4m3x2 (low byte = first value)
__device__ __forceinline__ uint16_t f32x2_to_e4m3x2(float v0, float v1) {
    uint16_t q;
    asm("cvt.rn.satfinite.e4m3x2.f32 %0, %1, %2;" : "=h"(q) : "f"(v1), "f"(v0));
    return q;
}
// fp8 pair -> half2
__device__ __forceinline__ __half2 e4m3x2_to_h2(uint16_t q) {
    uint32_t h;
    asm("cvt.rn.f16x2.e4m3x2 %0, %1;" : "=r"(h) : "h"(q));
    return *reinterpret_cast<__half2*>(&h);
}
// accumulate 4 fp8 (uint32) into 2 half2 accumulators
__device__ __forceinline__ void acch2_4(__half2* a, uint32_t v) {
    a[0] = __hadd2(a[0], e4m3x2_to_h2((uint16_t)(v & 0xFFFFu)));
    a[1] = __hadd2(a[1], e4m3x2_to_h2((uint16_t)(v >> 16)));
}
// accumulate 8 fp8 (uint2) into 4 half2 accumulators
__device__ __forceinline__ void acch2_8(__half2* a, uint2 v) {
    acch2_4(a, v.x);
    acch2_4(a + 2, v.y);
}
__device__ __forceinline__ void acc4h(float* a, uint2 v) {
    __half2* h = reinterpret_cast<__half2*>(&v);
#pragma unroll
    for (int i = 0; i < 2; i++) {
        float2 f = __half22float2(h[i]);
        a[2 * i]     += f.x;
        a[2 * i + 1] += f.y;
    }
}

// ================= graph preprocessing =================
__global__ void degree_kernel(const int* __restrict__ dst) {
    int e = blockIdx.x * blockDim.x + threadIdx.x;
    if (e < NEDGES) atomicAdd(&g_cnt[dst[e]], 1);
}
__global__ __launch_bounds__(1024) void scan_block_kernel() {   // also computes g_is
    __shared__ int ws[32];
    int t = threadIdx.x, b = blockIdx.x;
    int i = b * 1024 + t;
    int v = (i < NNODES) ? g_cnt[i] : 0;
    if (i < NNODES) g_is[i] = rsqrtf((float)v + 1.0f);
    int lane = t & 31, w = t >> 5;
    int x = v;
#pragma unroll
    for (int off = 1; off < 32; off <<= 1) {
        int y = __shfl_up_sync(0xffffffffu, x, off);
        if (lane >= off) x += y;
    }
    if (lane == 31) ws[w] = x;
    __syncthreads();
    if (w == 0) {
        int s = ws[lane];
#pragma unroll
        for (int off = 1; off < 32; off <<= 1) {
            int y = __shfl_up_sync(0xffffffffu, s, off);
            if (lane >= off) s += y;
        }
        ws[lane] = s;
    }
    __syncthreads();
    int incl = x + (w ? ws[w - 1] : 0);
    if (i < NNODES) g_rowptr[i] = incl - v;
    if (t == 1023) g_bsum[b] = incl;
}
__global__ void scan_tops_kernel() {
    __shared__ int s[64];
    int t = threadIdx.x;
    int v = (t < NB_SCAN) ? g_bsum[t] : 0;
    s[t] = v;
    __syncthreads();
    for (int off = 1; off < 64; off <<= 1) {
        int y = (t >= off) ? s[t - off] : 0;
        __syncthreads();
        s[t] += y;
        __syncthreads();
    }
    if (t < NB_SCAN) g_boff[t] = s[t] - v;
    if (t == NB_SCAN - 1) g_rowptr[NNODES] = s[t];
}
__global__ __launch_bounds__(1024) void scan_add_kernel() {
    int i = blockIdx.x * 1024 + threadIdx.x;
    if (i < NNODES) g_rowptr[i] += g_boff[blockIdx.x];
}
__global__ void fill_kernel(const int* __restrict__ src, const int* __restrict__ dst) {
    int e = blockIdx.x * blockDim.x + threadIdx.x;
    if (e < NEDGES) {
        int d = dst[e];
        int p = atomicAdd(&g_fill[d], 1);
        g_srcs[g_rowptr[d] + p] = src[e];
    }
}
// all 4 weights transposed -> bf16, one launch
#define W1E (FIN * HID)
#define W2E (HID * HID)
#define W3E (HID * HID)
#define W4E (HID * CPAD)
__global__ void wprep_all_kernel(const float* __restrict__ W1, const float* __restrict__ W2,
                                 const float* __restrict__ W3, const float* __restrict__ W4) {
    int i = blockIdx.x * blockDim.x + threadIdx.x;
    const float* W; __nv_bfloat16* dw;
    int K, Nw, j;
    if (i < W1E) { W = W1; dw = g_wt1; K = FIN; Nw = HID; j = i; }
    else if (i < W1E + W2E) { W = W2; dw = g_wt2; K = HID; Nw = HID; j = i - W1E; }
    else if (i < W1E + W2E + W3E) { W = W3; dw = g_wt3; K = HID; Nw = HID; j = i - W1E - W2E; }
    else if (i < W1E + W2E + W3E + W4E) { W = W4; dw = g_wt4; K = HID; Nw = NCLS; j = i - W1E - W2E - W3E; }
    else return;
    int n = j / K, k = j % K;
    float v = (n < Nw) ? W[k * Nw + n] : 0.0f;
    dw[j] = __float2bfloat16(v);
}
// x8[n][f] = fp8(is[n] * x[n][f])
__global__ void xprep_kernel(const float4* __restrict__ x) {
    int i = blockIdx.x * blockDim.x + threadIdx.x;   // one float4 (4 feats)
    if (i < NNODES * FIN / 4) {
        int n = i >> 5;                              // 32 float4 per node
        float isn = g_is[n];
        float4 v = x[i];
        uint16_t lo = f32x2_to_e4m3x2(isn * v.x, isn * v.y);
        uint16_t hi = f32x2_to_e4m3x2(isn * v.z, isn * v.w);
        reinterpret_cast<uint32_t*>(g_x8)[i] = (uint32_t)lo | ((uint32_t)hi << 16);
    }
}

// ================= aggregation kernels (fp8 gather, fp16 HADD2 accum) =================
// layer-1: warp per node; t[n] = is[n]*(sum_src x8[src] + x8[n]) -> bf16
__global__ __launch_bounds__(256) void agg_x_kernel() {
    int n = blockIdx.x * 8 + (threadIdx.x >> 5);
    int t = threadIdx.x & 31;                // 4 feats per thread
    if (n >= NNODES) return;
    const uint32_t* xr = reinterpret_cast<const uint32_t*>(g_x8);   // 32 u32 per row
    int beg = g_rowptr[n], end = g_rowptr[n + 1];
    __half2 a[2] = { __half2half2(__ushort_as_half(0)), __half2half2(__ushort_as_half(0)) };
    acch2_4(a, xr[(size_t)n * 32 + t]);      // self (already is-scaled)
    int e = beg;
    for (; e + 4 <= end; e += 4) {
        int s0 = g_srcs[e], s1 = g_srcs[e + 1], s2 = g_srcs[e + 2], s3 = g_srcs[e + 3];
        uint32_t u0 = xr[(size_t)s0 * 32 + t];
        uint32_t u1 = xr[(size_t)s1 * 32 + t];
        uint32_t u2 = xr[(size_t)s2 * 32 + t];
        uint32_t u3 = xr[(size_t)s3 * 32 + t];
        acch2_4(a, u0); acch2_4(a, u1); acch2_4(a, u2); acch2_4(a, u3);
    }
    for (; e < end; e++) acch2_4(a, xr[(size_t)g_srcs[e] * 32 + t]);
    float isn = g_is[n];
    float2 f0 = __half22float2(a[0]);
    float2 f1 = __half22float2(a[1]);
    float vv[4] = { isn * f0.x, isn * f0.y, isn * f1.x, isn * f1.y };
    unsigned short hh[4];
#pragma unroll
    for (int k = 0; k < 4; k++) {
        __nv_bfloat16 h = __float2bfloat16(vv[k]);
        hh[k] = *reinterpret_cast<unsigned short*>(&h);
    }
    *(uint2*)(g_t + (size_t)n * FIN + 4 * t) = *(uint2*)hh;
}
// mid layers: warp per node, fp8 gather (uint2 = 8 feats), fp16 HADD2 accum
__global__ __launch_bounds__(256) void agg_mid_kernel(
    const float* __restrict__ bias, __nv_bfloat16* __restrict__ oh) {
    int n = blockIdx.x * 8 + (threadIdx.x >> 5);
    int t = threadIdx.x & 31;                // feats [8t, 8t+8)
    if (n >= NNODES) return;
    const uint2* hr = reinterpret_cast<const uint2*>(g_hs8);   // 32 uint2 per row
    int beg = g_rowptr[n], end = g_rowptr[n + 1];
    __half2 a[4];
#pragma unroll
    for (int k = 0; k < 4; k++) a[k] = __half2half2(__ushort_as_half(0));
    acch2_8(a, hr[(size_t)n * 32 + t]);      // self
    int e = beg;
    for (; e + 4 <= end; e += 4) {
        int s0 = g_srcs[e], s1 = g_srcs[e + 1], s2 = g_srcs[e + 2], s3 = g_srcs[e + 3];
        uint2 u0 = hr[(size_t)s0 * 32 + t];
        uint2 u1 = hr[(size_t)s1 * 32 + t];
        uint2 u2 = hr[(size_t)s2 * 32 + t];
        uint2 u3 = hr[(size_t)s3 * 32 + t];
        acch2_8(a, u0); acch2_8(a, u1); acch2_8(a, u2); acch2_8(a, u3);
    }
    for (; e < end; e++) acch2_8(a, hr[(size_t)g_srcs[e] * 32 + t]);
    float isn = g_is[n];
    unsigned short hh[8];
#pragma unroll
    for (int k = 0; k < 4; k++) {
        float2 f = __half22float2(a[k]);
        __nv_bfloat16 h0 = __float2bfloat16(fmaxf(isn * f.x + bias[8 * t + 2 * k], 0.0f));
        __nv_bfloat16 h1 = __float2bfloat16(fmaxf(isn * f.y + bias[8 * t + 2 * k + 1], 0.0f));
        hh[2 * k]     = *reinterpret_cast<unsigned short*>(&h0);
        hh[2 * k + 1] = *reinterpret_cast<unsigned short*>(&h1);
    }
    *(uint4*)(oh + (size_t)n * HID + 8 * t) = *(uint4*)hh;
}
// layer 4: fp16 gather + fp32 accum (precision-critical), 16 thr/node; + log_softmax
__global__ __launch_bounds__(256) void agg40_lsm_kernel(
    const float* __restrict__ b4, float* __restrict__ out) {
    int n = blockIdx.x * 16 + (threadIdx.x >> 4);
    int t = threadIdx.x & 15;                // cols [4t, 4t+4)
    if (n >= NNODES) return;
    const uint2* hr = reinterpret_cast<const uint2*>(g_hs4h);
    int beg = g_rowptr[n], end = g_rowptr[n + 1];
    float a[4] = {0.f, 0.f, 0.f, 0.f};
    acc4h(a, hr[(size_t)n * 16 + t]);
    int e = beg;
    for (; e + 4 <= end; e += 4) {
        int s0 = g_srcs[e], s1 = g_srcs[e + 1], s2 = g_srcs[e + 2], s3 = g_srcs[e + 3];
        uint2 u0 = hr[(size_t)s0 * 16 + t];
        uint2 u1 = hr[(size_t)s1 * 16 + t];
        uint2 u2 = hr[(size_t)s2 * 16 + t];
        uint2 u3 = hr[(size_t)s3 * 16 + t];
        acc4h(a, u0); acc4h(a, u1); acc4h(a, u2); acc4h(a, u3);
    }
    for (; e < end; e++) acc4h(a, hr[(size_t)g_srcs[e] * 16 + t]);
    float sc = g_is[n];
    int col0 = 4 * t;
    float v[4];
#pragma unroll
    for (int k = 0; k < 4; k++)
        v[k] = (col0 + k < NCLS) ? (sc * a[k] + b4[col0 + k]) : -1e30f;
    float m = fmaxf(fmaxf(v[0], v[1]), fmaxf(v[2], v[3]));
#pragma unroll
    for (int off = 8; off; off >>= 1) m = fmaxf(m, __shfl_xor_sync(0xffffffffu, m, off));
    float se = 0.f;
#pragma unroll
    for (int k = 0; k < 4; k++) se += (col0 + k < NCLS) ? __expf(v[k] - m) : 0.f;
#pragma unroll
    for (int off = 8; off; off >>= 1) se += __shfl_xor_sync(0xffffffffu, se, off);
    float lse = m + __logf(se);
    if (t < 10) {
        float4 o;
        o.x = v[0] - lse; o.y = v[1] - lse; o.z = v[2] - lse; o.w = v[3] - lse;
        *(float4*)(out + (size_t)n * NCLS + col0) = o;
    }
}

// ================= single-bf16 HMMA GEMM, cp.async pipelined =================
// MODE 0: Ch = D*g_is[m] fp16 (layer 4); MODE 1: relu(D+bias) -> Cb bf16 (layer 1);
// MODE 2: C8 = fp8(D*g_is[m]) (layers 2/3).
#define ASTR 72

template <int KT, int BN_T, int MODE>
__global__ __launch_bounds__(256, 2) void mma_gemm_kernel(
    const __nv_bfloat16* __restrict__ A,
    const __nv_bfloat16* __restrict__ B,
    int NT,
    __half* __restrict__ Ch,
    uint8_t* __restrict__ C8,
    __nv_bfloat16* __restrict__ Cb,
    const float* __restrict__ bias)
{
    extern __shared__ __nv_bfloat16 sm[];
    constexpr int NCH = KT / 64;
    constexpr int BSTR = KT + 8;
    constexpr int ASTG_B = 128 * ASTR * 2;
    constexpr int ABUF_B = 2 * ASTG_B;

    const int tid = threadIdx.x;
    const int lane = tid & 31;
    const int wid = tid >> 5;
    const int wm = wid & 3;
    const int wn = wid >> 2;
    constexpr int WN = BN_T / 2;
    constexpr int NTILES = WN / 8;

    const int row0 = blockIdx.x * 128;
    const int col0 = blockIdx.y * BN_T;

    const uint32_t uS = smem_u32(sm);
    const uint32_t uB = uS + ABUF_B;

    auto loadA = [&](int c) {
        int k0 = c * 64;
        uint32_t ab = uS + (c & 1) * ASTG_B;
#pragma unroll
        for (int it = 0; it < 4; it++) {
            int idx = tid + it * 256;
            int r = idx >> 3, q = idx & 7;
            int gr = row0 + r;
            int sz = (gr < NNODES) ? 16 : 0;
            cp_async16(ab + (uint32_t)(r * ASTR + q * 8) * 2,
                       A + (size_t)gr * KT + k0 + q * 8, sz);
        }
    };

    {
        constexpr int BUNITS = BN_T * KT / 8;
        for (int u = tid; u < BUNITS; u += 256) {
            int n = u / (KT / 8), q = u % (KT / 8);
            cp_async16(uB + (uint32_t)(n * BSTR + q * 8) * 2,
                       B + (size_t)(col0 + n) * KT + q * 8, 16);
        }
        loadA(0);
        CP_COMMIT();
    }

    float acc[2][NTILES][4];
#pragma unroll
    for (int i = 0; i < 2; i++)
#pragma unroll
        for (int j = 0; j < NTILES; j++)
#pragma unroll
            for (int q = 0; q < 4; q++) acc[i][j][q] = 0.0f;

    const int a_r = (lane & 7) + ((lane >> 3) & 1) * 8;
    const int a_k = (lane >> 4) * 8;
    const int b_n = (lane & 7) + ((lane >> 4) & 1) * 8;
    const int b_k = ((lane >> 3) & 1) * 8;

#pragma unroll
    for (int c = 0; c < NCH; c++) {
        if (c + 1 < NCH) {
            loadA(c + 1);
            CP_COMMIT();
            asm volatile("cp.async.wait_group 1;");
        } else {
            asm volatile("cp.async.wait_group 0;");
        }
        __syncthreads();

        uint32_t ab = uS + (c & 1) * ASTG_B;
#pragma unroll
        for (int ks = 0; ks < 4; ks++) {
            uint32_t ah[2][4];
#pragma unroll
            for (int mt = 0; mt < 2; mt++) {
                uint32_t off = (uint32_t)(((wm * 32 + mt * 16 + a_r) * ASTR + ks * 16 + a_k) * 2);
                ldsm_x4(ah[mt][0], ah[mt][1], ah[mt][2], ah[mt][3], ab + off);
            }
            uint32_t bh[NTILES][2];
#pragma unroll
            for (int nb = 0; nb < NTILES / 2; nb++) {
                uint32_t off = (uint32_t)(((wn * WN + nb * 16 + b_n) * BSTR + c * 64 + ks * 16 + b_k) * 2);
                uint32_t r0, r1, r2, r3;
                ldsm_x4(r0, r1, r2, r3, uB + off);
                bh[nb * 2][0] = r0; bh[nb * 2][1] = r1;
                bh[nb * 2 + 1][0] = r2; bh[nb * 2 + 1][1] = r3;
            }
#pragma unroll
            for (int mt = 0; mt < 2; mt++)
#pragma unroll
                for (int nt = 0; nt < NTILES; nt++)
                    mma16816(acc[mt][nt][0], acc[mt][nt][1], acc[mt][nt][2], acc[mt][nt][3],
                             ah[mt][0], ah[mt][1], ah[mt][2], ah[mt][3], bh[nt][0], bh[nt][1]);
        }
        __syncthreads();
    }

    // ---- epilogue ----
    const int rbase = row0 + wm * 32 + (lane >> 2);
    const int cbase = col0 + wn * WN + ((lane & 3) * 2);
#pragma unroll
    for (int mt = 0; mt < 2; mt++) {
#pragma unroll
        for (int half = 0; half < 2; half++) {
            int gr = rbase + mt * 16 + half * 8;
            if (gr < NNODES) {
                if (MODE == 0) {
                    float s = g_is[gr];
#pragma unroll
                    for (int nt = 0; nt < NTILES; nt++) {
                        __half2 p = __floats2half2_rn(acc[mt][nt][half * 2 + 0] * s,
                                                      acc[mt][nt][half * 2 + 1] * s);
                        *(__half2*)(Ch + (size_t)gr * NT + cbase + nt * 8) = p;
                    }
                } else if (MODE == 2) {
                    float s = g_is[gr];
#pragma unroll
                    for (int nt = 0; nt < NTILES; nt++) {
                        uint16_t q = f32x2_to_e4m3x2(acc[mt][nt][half * 2 + 0] * s,
                                                     acc[mt][nt][half * 2 + 1] * s);
                        *(uint16_t*)(C8 + (size_t)gr * NT + cbase + nt * 8) = q;
                    }
                } else {
#pragma unroll
                    for (int nt = 0; nt < NTILES; nt++) {
                        int c = cbase + nt * 8;
                        float v0 = fmaxf(acc[mt][nt][half * 2 + 0] + bias[c], 0.0f);
                        float v1 = fmaxf(acc[mt][nt][half * 2 + 1] + bias[c + 1], 0.0f);
                        __nv_bfloat162 hp;
                        hp.x = __float2bfloat16(v0);
                        hp.y = __float2bfloat16(v1);
                        *(__nv_bfloat162*)(Cb + (size_t)gr * NT + c) = hp;
                    }
                }
            }
        }
    }
}

// ================= launch =================
extern "C" void kernel_launch(void* const* d_in, const int* in_sizes, int n_in,
                              void* d_out, int out_size)
{
    const float* x  = (const float*)d_in[0];
    const int*   ei = (const int*)  d_in[1];
    const float* W1 = (const float*)d_in[2];
    const float* b1 = (const float*)d_in[3];
    const float* W2 = (const float*)d_in[4];
    const float* b2 = (const float*)d_in[5];
    const float* W3 = (const float*)d_in[6];
    const float* b3 = (const float*)d_in[7];
    const float* W4 = (const float*)d_in[8];
    const float* b4 = (const float*)d_in[9];
    float* out = (float*)d_out;

    const int* src = ei;
    const int* dst = ei + NEDGES;

    __nv_bfloat16 *tptr, *h0, *h1, *wt1, *wt2, *wt3, *wt4;
    __half* hs4h;
    uint8_t* hs8;
    int *cntp, *fillp;
    cudaGetSymbolAddress((void**)&tptr, g_t);
    cudaGetSymbolAddress((void**)&h0,  g_h0);
    cudaGetSymbolAddress((void**)&h1,  g_h1);
    cudaGetSymbolAddress((void**)&wt1, g_wt1);
    cudaGetSymbolAddress((void**)&wt2, g_wt2);
    cudaGetSymbolAddress((void**)&wt3, g_wt3);
    cudaGetSymbolAddress((void**)&wt4, g_wt4);
    cudaGetSymbolAddress((void**)&hs8,  g_hs8);
    cudaGetSymbolAddress((void**)&hs4h, g_hs4h);
    cudaGetSymbolAddress((void**)&cntp, g_cnt);
    cudaGetSymbolAddress((void**)&fillp, g_fill);

    const int SMEM_L1 = 36864 + 128 * (128 + 8) * 2;  // 71680
    const int SMEM_L2 = 36864 + 128 * (256 + 8) * 2;  // 104448
    const int SMEM_L4 = 36864 + 64  * (256 + 8) * 2;  // 70656
    cudaFuncSetAttribute(mma_gemm_kernel<128, 128, 1>, cudaFuncAttributeMaxDynamicSharedMemorySize, SMEM_L1);
    cudaFuncSetAttribute(mma_gemm_kernel<256, 128, 2>, cudaFuncAttributeMaxDynamicSharedMemorySize, SMEM_L2);
    cudaFuncSetAttribute(mma_gemm_kernel<256, 64, 0>,  cudaFuncAttributeMaxDynamicSharedMemorySize, SMEM_L4);

    const int TB = 256;
    int edgeBlocks = (NEDGES + TB - 1) / TB;

    // ---- graph build ----
    cudaMemsetAsync(cntp, 0, NNODES * sizeof(int));
    cudaMemsetAsync(fillp, 0, NNODES * sizeof(int));
    degree_kernel<<<edgeBlocks, TB>>>(dst);
    scan_block_kernel<<<NB_SCAN, 1024>>>();
    scan_tops_kernel<<<1, 64>>>();
    scan_add_kernel<<<NB_SCAN, 1024>>>();
    fill_kernel<<<edgeBlocks, TB>>>(src, dst);

    // ---- weight + x prep ----
    const int WALL = W1E + W2E + W3E + W4E;
    wprep_all_kernel<<<(WALL + TB - 1) / TB, TB>>>(W1, W2, W3, W4);
    xprep_kernel<<<(NNODES * FIN / 4 + TB - 1) / TB, TB>>>((const float4*)x);

    int mBlocks = (NNODES + 127) / 128;          // 391
    dim3 gHID(mBlocks, 2);
    dim3 gC(mBlocks, 1);
    int warpNodeBlocks = (NNODES + 7) / 8;       // 6250
    int a40Blocks = (NNODES + 15) / 16;          // 3125

    // layer 1: aggregate-first (fp8 gather, fp16 accum), GEMM fused bias+relu
    agg_x_kernel<<<warpNodeBlocks, TB>>>();
    mma_gemm_kernel<128, 128, 1><<<gHID, 256, SMEM_L1>>>(
        tptr, wt1, HID, nullptr, nullptr, h0, b1);
    // layer 2 (fp8 gather table)
    mma_gemm_kernel<256, 128, 2><<<gHID, 256, SMEM_L2>>>(
        h0, wt2, HID, nullptr, hs8, nullptr, nullptr);
    agg_mid_kernel<<<warpNodeBlocks, TB>>>(b2, h1);
    // layer 3 (fp8 gather table)
    mma_gemm_kernel<256, 128, 2><<<gHID, 256, SMEM_L2>>>(
        h1, wt3, HID, nullptr, hs8, nullptr, nullptr);
    agg_mid_kernel<<<warpNodeBlocks, TB>>>(b3, h0);
    // layer 4 (fp16 table — precision-critical) + log_softmax
    mma_gemm_kernel<256, 64, 0><<<gC, 256, SMEM_L4>>>(
        h0, wt4, CPAD, hs4h, nullptr, nullptr, nullptr);
    agg40_lsm_kernel<<<a40Blocks, TB>>>(b4, out);
}

// round 16
// speedup vs baseline: 1.1224x; 1.0188x over previous
#include <cuda_runtime.h>
#include <cuda_bf16.h>
#include <cuda_fp16.h>
#include <cstdint>
#include <cstddef>

#define NNODES 50000
#define NEDGES 1600000
#define FIN    128
#define HID    256
#define NCLS   40
#define CPAD   64
#define NB_SCAN 49   // ceil(50000/1024)

// ================= static device scratch =================
__device__ float g_is[NNODES];
__device__ int   g_cnt[NNODES];     // zeroed by agg40_lsm tail each launch (zero-init at load)
__device__ int   g_fill[NNODES];    // ditto
__device__ int   g_rowptr[NNODES + 1];
__device__ int   g_srcs[NEDGES];
__device__ int   g_bsum[NB_SCAN];

__device__ uint8_t g_x8[(size_t)NNODES * FIN];    // is[n]*x[n] in fp8 e4m3
__device__ uint8_t g_hs8[(size_t)NNODES * HID];   // layers 2/3 gather table, fp8 e4m3
__device__ __half  g_hs4h[(size_t)NNODES * CPAD]; // layer-4 gather table, fp16 (precision!)

__device__ __nv_bfloat16 g_t[(size_t)NNODES * FIN];    // layer-1 GEMM input (bf16)
__device__ __nv_bfloat16 g_h0[(size_t)NNODES * HID];   // activations bf16
__device__ __nv_bfloat16 g_h1[(size_t)NNODES * HID];

// weights transposed (bf16): Wt[n][k] row-major [Npad][K]
__device__ __nv_bfloat16 g_wt1[HID * FIN];
__device__ __nv_bfloat16 g_wt2[HID * HID];
__device__ __nv_bfloat16 g_wt3[HID * HID];
__device__ __nv_bfloat16 g_wt4[CPAD * HID];

#define W1E (FIN * HID)
#define W2E (HID * HID)
#define W3E (HID * HID)
#define W4E (HID * CPAD)
#define WALL_E (W1E + W2E + W3E + W4E)

// ================= PTX helpers (base compute_103-legal only) =================
__device__ __forceinline__ uint32_t smem_u32(const void* p) {
    uint32_t a;
    asm("{ .reg .u64 t; cvta.to.shared.u64 t, %1; cvt.u32.u64 %0, t; }" : "=r"(a) : "l"(p));
    return a;
}
__device__ __forceinline__ void ldsm_x4(uint32_t& r0, uint32_t& r1, uint32_t& r2, uint32_t& r3,
                                        uint32_t addr) {
    asm volatile("ldmatrix.sync.aligned.m8n8.x4.shared.b16 {%0,%1,%2,%3}, [%4];"
                 : "=r"(r0), "=r"(r1), "=r"(r2), "=r"(r3) : "r"(addr));
}
__device__ __forceinline__ void mma16816(float& c0, float& c1, float& c2, float& c3,
                                         uint32_t a0, uint32_t a1, uint32_t a2, uint32_t a3,
                                         uint32_t b0, uint32_t b1) {
    asm volatile("mma.sync.aligned.m16n8k16.row.col.f32.bf16.bf16.f32 "
                 "{%0,%1,%2,%3}, {%4,%5,%6,%7}, {%8,%9}, {%0,%1,%2,%3};"
                 : "+f"(c0), "+f"(c1), "+f"(c2), "+f"(c3)
                 : "r"(a0), "r"(a1), "r"(a2), "r"(a3), "r"(b0), "r"(b1));
}
__device__ __forceinline__ void cp_async16(uint32_t dst, const void* src, int sz) {
    asm volatile("cp.async.cg.shared.global [%0], [%1], 16, %2;"
                 :: "r"(dst), "l"(src), "r"(sz));
}
#define CP_COMMIT() asm volatile("cp.async.commit_group;")

// pack two f32 -> e4m3x2 (low byte = first value)
__device__ __forceinline__ uint16_t f32x2_to_e4m3x2(float v0, float v1) {
    uint16_t q;
    asm("cvt.rn.satfinite.e4m3x2.f32 %0, %1, %2;" : "=h"(q) : "f"(v1), "f"(v0));
    return q;
}
// fp8 pair -> half2
__device__ __forceinline__ __half2 e4m3x2_to_h2(uint16_t q) {
    uint32_t h;
    asm("cvt.rn.f16x2.e4m3x2 %0, %1;" : "=r"(h) : "h"(q));
    return *reinterpret_cast<__half2*>(&h);
}
// accumulate 4 fp8 (uint32) into 2 half2 accumulators
__device__ __forceinline__ void acch2_4(__half2* a, uint32_t v) {
    a[0] = __hadd2(a[0], e4m3x2_to_h2((uint16_t)(v & 0xFFFFu)));
    a[1] = __hadd2(a[1], e4m3x2_to_h2((uint16_t)(v >> 16)));
}
// accumulate 8 fp8 (uint2) into 4 half2 accumulators
__device__ __forceinline__ void acch2_8(__half2* a, uint2 v) {
    acch2_4(a, v.x);
    acch2_4(a + 2, v.y);
}
__device__ __forceinline__ void acc4h(float* a, uint2 v) {
    __half2* h = reinterpret_cast<__half2*>(&v);
#pragma unroll
    for (int i = 0; i < 2; i++) {
        float2 f = __half22float2(h[i]);
        a[2 * i]     += f.x;
        a[2 * i + 1] += f.y;
    }
}

// ================= graph preprocessing =================
__global__ void degree_kernel(const int* __restrict__ dst) {
    int e = blockIdx.x * blockDim.x + threadIdx.x;
    if (e < NEDGES) atomicAdd(&g_cnt[dst[e]], 1);
}
// block-local scan of degrees + g_is + x->fp8 prep + weight transpose prep (fused)
__global__ __launch_bounds__(1024) void scan_block_kernel(
    const float4* __restrict__ x,
    const float* __restrict__ W1, const float* __restrict__ W2,
    const float* __restrict__ W3, const float* __restrict__ W4) {
    __shared__ int ws[32];
    __shared__ float sis[1024];
    int t = threadIdx.x, b = blockIdx.x;
    int i = b * 1024 + t;
    int v = (i < NNODES) ? g_cnt[i] : 0;
    float isn = rsqrtf((float)v + 1.0f);
    if (i < NNODES) g_is[i] = isn;
    sis[t] = isn;
    int lane = t & 31, w = t >> 5;
    int x_ = v;
#pragma unroll
    for (int off = 1; off < 32; off <<= 1) {
        int y = __shfl_up_sync(0xffffffffu, x_, off);
        if (lane >= off) x_ += y;
    }
    if (lane == 31) ws[w] = x_;
    __syncthreads();
    if (w == 0) {
        int s = ws[lane];
#pragma unroll
        for (int off = 1; off < 32; off <<= 1) {
            int y = __shfl_up_sync(0xffffffffu, s, off);
            if (lane >= off) s += y;
        }
        ws[lane] = s;
    }
    __syncthreads();
    int incl = x_ + (w ? ws[w - 1] : 0);
    if (i < NNODES) g_rowptr[i] = incl - v;
    if (t == 1023) g_bsum[b] = incl;

    // --- fused xprep: 32768 float4 per block, coalesced; sis visible (barriers above) ---
    int base_f4 = b * 32768;
#pragma unroll
    for (int it = 0; it < 32; it++) {
        int li = it * 1024 + t;
        int gf4 = base_f4 + li;
        if (gf4 < NNODES * 32) {
            float s = sis[li >> 5];
            float4 vv = x[gf4];
            uint16_t lo = f32x2_to_e4m3x2(s * vv.x, s * vv.y);
            uint16_t hi = f32x2_to_e4m3x2(s * vv.z, s * vv.w);
            reinterpret_cast<uint32_t*>(g_x8)[gf4] = (uint32_t)lo | ((uint32_t)hi << 16);
        }
    }
    // --- fused wprep: grid-stride over all 4 weight matrices ---
    for (int j = b * 1024 + t; j < WALL_E; j += NB_SCAN * 1024) {
        const float* W; __nv_bfloat16* dw;
        int K, Nw, jj;
        if (j < W1E) { W = W1; dw = g_wt1; K = FIN; Nw = HID; jj = j; }
        else if (j < W1E + W2E) { W = W2; dw = g_wt2; K = HID; Nw = HID; jj = j - W1E; }
        else if (j < W1E + W2E + W3E) { W = W3; dw = g_wt3; K = HID; Nw = HID; jj = j - W1E - W2E; }
        else { W = W4; dw = g_wt4; K = HID; Nw = NCLS; jj = j - W1E - W2E - W3E; }
        int n = jj / K, k = jj % K;
        float vv = (n < Nw) ? W[k * Nw + n] : 0.0f;
        dw[jj] = __float2bfloat16(vv);
    }
}
// merged: scan block sums + apply offsets (replaces scan_tops + scan_add)
__global__ __launch_bounds__(1024) void scan_finish_kernel() {
    __shared__ int s[64];
    int t = threadIdx.x, b = blockIdx.x;
    if (t < 64) s[t] = (t < NB_SCAN) ? g_bsum[t] : 0;
    __syncthreads();
    for (int off = 1; off < 64; off <<= 1) {
        int y = (t < 64 && t >= off) ? s[t - off] : 0;
        __syncthreads();
        if (t < 64) s[t] += y;
        __syncthreads();
    }
    int boff = (b > 0) ? s[b - 1] : 0;
    int i = b * 1024 + t;
    if (i < NNODES) g_rowptr[i] += boff;
    if (b == NB_SCAN - 1 && t == 0) g_rowptr[NNODES] = s[NB_SCAN - 1];
}
__global__ void fill_kernel(const int* __restrict__ src, const int* __restrict__ dst) {
    int e = blockIdx.x * blockDim.x + threadIdx.x;
    if (e < NEDGES) {
        int d = dst[e];
        int p = atomicAdd(&g_fill[d], 1);
        g_srcs[g_rowptr[d] + p] = src[e];
    }
}

// ================= aggregation kernels (fp8 gather, fp16 HADD2 accum) =================
// layer-1: warp per node; t[n] = is[n]*(sum_src x8[src] + x8[n]) -> bf16
__global__ __launch_bounds__(256) void agg_x_kernel() {
    int n = blockIdx.x * 8 + (threadIdx.x >> 5);
    int t = threadIdx.x & 31;                // 4 feats per thread
    if (n >= NNODES) return;
    const uint32_t* xr = reinterpret_cast<const uint32_t*>(g_x8);   // 32 u32 per row
    int beg = g_rowptr[n], end = g_rowptr[n + 1];
    __half2 a[2] = { __half2half2(__ushort_as_half(0)), __half2half2(__ushort_as_half(0)) };
    acch2_4(a, xr[(size_t)n * 32 + t]);      // self (already is-scaled)
    int e = beg;
    for (; e + 4 <= end; e += 4) {
        int s0 = g_srcs[e], s1 = g_srcs[e + 1], s2 = g_srcs[e + 2], s3 = g_srcs[e + 3];
        uint32_t u0 = xr[(size_t)s0 * 32 + t];
        uint32_t u1 = xr[(size_t)s1 * 32 + t];
        uint32_t u2 = xr[(size_t)s2 * 32 + t];
        uint32_t u3 = xr[(size_t)s3 * 32 + t];
        acch2_4(a, u0); acch2_4(a, u1); acch2_4(a, u2); acch2_4(a, u3);
    }
    for (; e < end; e++) acch2_4(a, xr[(size_t)g_srcs[e] * 32 + t]);
    float isn = g_is[n];
    float2 f0 = __half22float2(a[0]);
    float2 f1 = __half22float2(a[1]);
    float vv[4] = { isn * f0.x, isn * f0.y, isn * f1.x, isn * f1.y };
    unsigned short hh[4];
#pragma unroll
    for (int k = 0; k < 4; k++) {
        __nv_bfloat16 h = __float2bfloat16(vv[k]);
        hh[k] = *reinterpret_cast<unsigned short*>(&h);
    }
    *(uint2*)(g_t + (size_t)n * FIN + 4 * t) = *(uint2*)hh;
}
// mid layers: warp per node, fp8 gather (uint2 = 8 feats), fp16 HADD2 accum
__global__ __launch_bounds__(256) void agg_mid_kernel(
    const float* __restrict__ bias, __nv_bfloat16* __restrict__ oh) {
    int n = blockIdx.x * 8 + (threadIdx.x >> 5);
    int t = threadIdx.x & 31;                // feats [8t, 8t+8)
    if (n >= NNODES) return;
    const uint2* hr = reinterpret_cast<const uint2*>(g_hs8);   // 32 uint2 per row
    int beg = g_rowptr[n], end = g_rowptr[n + 1];
    __half2 a[4];
#pragma unroll
    for (int k = 0; k < 4; k++) a[k] = __half2half2(__ushort_as_half(0));
    acch2_8(a, hr[(size_t)n * 32 + t]);      // self
    int e = beg;
    for (; e + 4 <= end; e += 4) {
        int s0 = g_srcs[e], s1 = g_srcs[e + 1], s2 = g_srcs[e + 2], s3 = g_srcs[e + 3];
        uint2 u0 = hr[(size_t)s0 * 32 + t];
        uint2 u1 = hr[(size_t)s1 * 32 + t];
        uint2 u2 = hr[(size_t)s2 * 32 + t];
        uint2 u3 = hr[(size_t)s3 * 32 + t];
        acch2_8(a, u0); acch2_8(a, u1); acch2_8(a, u2); acch2_8(a, u3);
    }
    for (; e < end; e++) acch2_8(a, hr[(size_t)g_srcs[e] * 32 + t]);
    float isn = g_is[n];
    unsigned short hh[8];
#pragma unroll
    for (int k = 0; k < 4; k++) {
        float2 f = __half22float2(a[k]);
        __nv_bfloat16 h0 = __float2bfloat16(fmaxf(isn * f.x + bias[8 * t + 2 * k], 0.0f));
        __nv_bfloat16 h1 = __float2bfloat16(fmaxf(isn * f.y + bias[8 * t + 2 * k + 1], 0.0f));
        hh[2 * k]     = *reinterpret_cast<unsigned short*>(&h0);
        hh[2 * k + 1] = *reinterpret_cast<unsigned short*>(&h1);
    }
    *(uint4*)(oh + (size_t)n * HID + 8 * t) = *(uint4*)hh;
}
// layer 4: fp16 gather + fp32 accum (precision-critical), 16 thr/node; + log_softmax.
// Also zeroes g_cnt / g_fill for the next launch (pipeline tail; deterministic).
__global__ __launch_bounds__(256) void agg40_lsm_kernel(
    const float* __restrict__ b4, float* __restrict__ out) {
    int gi = blockIdx.x * blockDim.x + threadIdx.x;
    if (gi < NNODES) { g_cnt[gi] = 0; g_fill[gi] = 0; }
    int n = blockIdx.x * 16 + (threadIdx.x >> 4);
    int t = threadIdx.x & 15;                // cols [4t, 4t+4)
    if (n >= NNODES) return;
    const uint2* hr = reinterpret_cast<const uint2*>(g_hs4h);
    int beg = g_rowptr[n], end = g_rowptr[n + 1];
    float a[4] = {0.f, 0.f, 0.f, 0.f};
    acc4h(a, hr[(size_t)n * 16 + t]);
    int e = beg;
    for (; e + 4 <= end; e += 4) {
        int s0 = g_srcs[e], s1 = g_srcs[e + 1], s2 = g_srcs[e + 2], s3 = g_srcs[e + 3];
        uint2 u0 = hr[(size_t)s0 * 16 + t];
        uint2 u1 = hr[(size_t)s1 * 16 + t];
        uint2 u2 = hr[(size_t)s2 * 16 + t];
        uint2 u3 = hr[(size_t)s3 * 16 + t];
        acc4h(a, u0); acc4h(a, u1); acc4h(a, u2); acc4h(a, u3);
    }
    for (; e < end; e++) acc4h(a, hr[(size_t)g_srcs[e] * 16 + t]);
    float sc = g_is[n];
    int col0 = 4 * t;
    float v[4];
#pragma unroll
    for (int k = 0; k < 4; k++)
        v[k] = (col0 + k < NCLS) ? (sc * a[k] + b4[col0 + k]) : -1e30f;
    float m = fmaxf(fmaxf(v[0], v[1]), fmaxf(v[2], v[3]));
#pragma unroll
    for (int off = 8; off; off >>= 1) m = fmaxf(m, __shfl_xor_sync(0xffffffffu, m, off));
    float se = 0.f;
#pragma unroll
    for (int k = 0; k < 4; k++) se += (col0 + k < NCLS) ? __expf(v[k] - m) : 0.f;
#pragma unroll
    for (int off = 8; off; off >>= 1) se += __shfl_xor_sync(0xffffffffu, se, off);
    float lse = m + __logf(se);
    if (t < 10) {
        float4 o;
        o.x = v[0] - lse; o.y = v[1] - lse; o.z = v[2] - lse; o.w = v[3] - lse;
        *(float4*)(out + (size_t)n * NCLS + col0) = o;
    }
}

// ================= single-bf16 HMMA GEMM, cp.async pipelined =================
// MODE 0: Ch = D*g_is[m] fp16 (layer 4); MODE 1: relu(D+bias) -> Cb bf16 (layer 1);
// MODE 2: C8 = fp8(D*g_is[m]) (layers 2/3).
#define ASTR 72

template <int KT, int BN_T, int MODE>
__global__ __launch_bounds__(256, 2) void mma_gemm_kernel(
    const __nv_bfloat16* __restrict__ A,
    const __nv_bfloat16* __restrict__ B,
    int NT,
    __half* __restrict__ Ch,
    uint8_t* __restrict__ C8,
    __nv_bfloat16* __restrict__ Cb,
    const float* __restrict__ bias)
{
    extern __shared__ __nv_bfloat16 sm[];
    constexpr int NCH = KT / 64;
    constexpr int BSTR = KT + 8;
    constexpr int ASTG_B = 128 * ASTR * 2;
    constexpr int ABUF_B = 2 * ASTG_B;

    const int tid = threadIdx.x;
    const int lane = tid & 31;
    const int wid = tid >> 5;
    const int wm = wid & 3;
    const int wn = wid >> 2;
    constexpr int WN = BN_T / 2;
    constexpr int NTILES = WN / 8;

    const int row0 = blockIdx.x * 128;
    const int col0 = blockIdx.y * BN_T;

    const uint32_t uS = smem_u32(sm);
    const uint32_t uB = uS + ABUF_B;

    auto loadA = [&](int c) {
        int k0 = c * 64;
        uint32_t ab = uS + (c & 1) * ASTG_B;
#pragma unroll
        for (int it = 0; it < 4; it++) {
            int idx = tid + it * 256;
            int r = idx >> 3, q = idx & 7;
            int gr = row0 + r;
            int sz = (gr < NNODES) ? 16 : 0;
            cp_async16(ab + (uint32_t)(r * ASTR + q * 8) * 2,
                       A + (size_t)gr * KT + k0 + q * 8, sz);
        }
    };

    {
        constexpr int BUNITS = BN_T * KT / 8;
        for (int u = tid; u < BUNITS; u += 256) {
            int n = u / (KT / 8), q = u % (KT / 8);
            cp_async16(uB + (uint32_t)(n * BSTR + q * 8) * 2,
                       B + (size_t)(col0 + n) * KT + q * 8, 16);
        }
        loadA(0);
        CP_COMMIT();
    }

    float acc[2][NTILES][4];
#pragma unroll
    for (int i = 0; i < 2; i++)
#pragma unroll
        for (int j = 0; j < NTILES; j++)
#pragma unroll
            for (int q = 0; q < 4; q++) acc[i][j][q] = 0.0f;

    const int a_r = (lane & 7) + ((lane >> 3) & 1) * 8;
    const int a_k = (lane >> 4) * 8;
    const int b_n = (lane & 7) + ((lane >> 4) & 1) * 8;
    const int b_k = ((lane >> 3) & 1) * 8;

#pragma unroll
    for (int c = 0; c < NCH; c++) {
        if (c + 1 < NCH) {
            loadA(c + 1);
            CP_COMMIT();
            asm volatile("cp.async.wait_group 1;");
        } else {
            asm volatile("cp.async.wait_group 0;");
        }
        __syncthreads();

        uint32_t ab = uS + (c & 1) * ASTG_B;
#pragma unroll
        for (int ks = 0; ks < 4; ks++) {
            uint32_t ah[2][4];
#pragma unroll
            for (int mt = 0; mt < 2; mt++) {
                uint32_t off = (uint32_t)(((wm * 32 + mt * 16 + a_r) * ASTR + ks * 16 + a_k) * 2);
                ldsm_x4(ah[mt][0], ah[mt][1], ah[mt][2], ah[mt][3], ab + off);
            }
            uint32_t bh[NTILES][2];
#pragma unroll
            for (int nb = 0; nb < NTILES / 2; nb++) {
                uint32_t off = (uint32_t)(((wn * WN + nb * 16 + b_n) * BSTR + c * 64 + ks * 16 + b_k) * 2);
                uint32_t r0, r1, r2, r3;
                ldsm_x4(r0, r1, r2, r3, uB + off);
                bh[nb * 2][0] = r0; bh[nb * 2][1] = r1;
                bh[nb * 2 + 1][0] = r2; bh[nb * 2 + 1][1] = r3;
            }
#pragma unroll
            for (int mt = 0; mt < 2; mt++)
#pragma unroll
                for (int nt = 0; nt < NTILES; nt++)
                    mma16816(acc[mt][nt][0], acc[mt][nt][1], acc[mt][nt][2], acc[mt][nt][3],
                             ah[mt][0], ah[mt][1], ah[mt][2], ah[mt][3], bh[nt][0], bh[nt][1]);
        }
        __syncthreads();
    }

    // ---- epilogue ----
    const int rbase = row0 + wm * 32 + (lane >> 2);
    const int cbase = col0 + wn * WN + ((lane & 3) * 2);
#pragma unroll
    for (int mt = 0; mt < 2; mt++) {
#pragma unroll
        for (int half = 0; half < 2; half++) {
            int gr = rbase + mt * 16 + half * 8;
            if (gr < NNODES) {
                if (MODE == 0) {
                    float s = g_is[gr];
#pragma unroll
                    for (int nt = 0; nt < NTILES; nt++) {
                        __half2 p = __floats2half2_rn(acc[mt][nt][half * 2 + 0] * s,
                                                      acc[mt][nt][half * 2 + 1] * s);
                        *(__half2*)(Ch + (size_t)gr * NT + cbase + nt * 8) = p;
                    }
                } else if (MODE == 2) {
                    float s = g_is[gr];
#pragma unroll
                    for (int nt = 0; nt < NTILES; nt++) {
                        uint16_t q = f32x2_to_e4m3x2(acc[mt][nt][half * 2 + 0] * s,
                                                     acc[mt][nt][half * 2 + 1] * s);
                        *(uint16_t*)(C8 + (size_t)gr * NT + cbase + nt * 8) = q;
                    }
                } else {
#pragma unroll
                    for (int nt = 0; nt < NTILES; nt++) {
                        int c = cbase + nt * 8;
                        float v0 = fmaxf(acc[mt][nt][half * 2 + 0] + bias[c], 0.0f);
                        float v1 = fmaxf(acc[mt][nt][half * 2 + 1] + bias[c + 1], 0.0f);
                        __nv_bfloat162 hp;
                        hp.x = __float2bfloat16(v0);
                        hp.y = __float2bfloat16(v1);
                        *(__nv_bfloat162*)(Cb + (size_t)gr * NT + c) = hp;
                    }
                }
            }
        }
    }
}

// ================= launch =================
extern "C" void kernel_launch(void* const* d_in, const int* in_sizes, int n_in,
                              void* d_out, int out_size)
{
    const float* x  = (const float*)d_in[0];
    const int*   ei = (const int*)  d_in[1];
    const float* W1 = (const float*)d_in[2];
    const float* b1 = (const float*)d_in[3];
    const float* W2 = (const float*)d_in[4];
    const float* b2 = (const float*)d_in[5];
    const float* W3 = (const float*)d_in[6];
    const float* b3 = (const float*)d_in[7];
    const float* W4 = (const float*)d_in[8];
    const float* b4 = (const float*)d_in[9];
    float* out = (float*)d_out;

    const int* src = ei;
    const int* dst = ei + NEDGES;

    __nv_bfloat16 *tptr, *h0, *h1, *wt1, *wt2, *wt3, *wt4;
    __half* hs4h;
    uint8_t* hs8;
    cudaGetSymbolAddress((void**)&tptr, g_t);
    cudaGetSymbolAddress((void**)&h0,  g_h0);
    cudaGetSymbolAddress((void**)&h1,  g_h1);
    cudaGetSymbolAddress((void**)&wt1, g_wt1);
    cudaGetSymbolAddress((void**)&wt2, g_wt2);
    cudaGetSymbolAddress((void**)&wt3, g_wt3);
    cudaGetSymbolAddress((void**)&wt4, g_wt4);
    cudaGetSymbolAddress((void**)&hs8,  g_hs8);
    cudaGetSymbolAddress((void**)&hs4h, g_hs4h);

    const int SMEM_L1 = 36864 + 128 * (128 + 8) * 2;  // 71680
    const int SMEM_L2 = 36864 + 128 * (256 + 8) * 2;  // 104448
    const int SMEM_L4 = 36864 + 64  * (256 + 8) * 2;  // 70656
    cudaFuncSetAttribute(mma_gemm_kernel<128, 128, 1>, cudaFuncAttributeMaxDynamicSharedMemorySize, SMEM_L1);
    cudaFuncSetAttribute(mma_gemm_kernel<256, 128, 2>, cudaFuncAttributeMaxDynamicSharedMemorySize, SMEM_L2);
    cudaFuncSetAttribute(mma_gemm_kernel<256, 64, 0>,  cudaFuncAttributeMaxDynamicSharedMemorySize, SMEM_L4);

    const int TB = 256;
    int edgeBlocks = (NEDGES + TB - 1) / TB;

    // ---- graph build + fused preps (g_cnt/g_fill pre-zeroed by previous launch tail) ----
    degree_kernel<<<edgeBlocks, TB>>>(dst);
    scan_block_kernel<<<NB_SCAN, 1024>>>((const float4*)x, W1, W2, W3, W4);
    scan_finish_kernel<<<NB_SCAN, 1024>>>();
    fill_kernel<<<edgeBlocks, TB>>>(src, dst);

    int mBlocks = (NNODES + 127) / 128;          // 391
    dim3 gHID(mBlocks, 2);
    dim3 gC(mBlocks, 1);
    int warpNodeBlocks = (NNODES + 7) / 8;       // 6250
    int a40Blocks = (NNODES + 15) / 16;          // 3125

    // layer 1: aggregate-first (fp8 gather, fp16 accum), GEMM fused bias+relu
    agg_x_kernel<<<warpNodeBlocks, TB>>>();
    mma_gemm_kernel<128, 128, 1><<<gHID, 256, SMEM_L1>>>(
        tptr, wt1, HID, nullptr, nullptr, h0, b1);
    // layer 2 (fp8 gather table)
    mma_gemm_kernel<256, 128, 2><<<gHID, 256, SMEM_L2>>>(
        h0, wt2, HID, nullptr, hs8, nullptr, nullptr);
    agg_mid_kernel<<<warpNodeBlocks, TB>>>(b2, h1);
    // layer 3 (fp8 gather table)
    mma_gemm_kernel<256, 128, 2><<<gHID, 256, SMEM_L2>>>(
        h1, wt3, HID, nullptr, hs8, nullptr, nullptr);
    agg_mid_kernel<<<warpNodeBlocks, TB>>>(b3, h0);
    // layer 4 (fp16 table — precision-critical) + log_softmax + counter re-zero
    mma_gemm_kernel<256, 64, 0><<<gC, 256, SMEM_L4>>>(
        h0, wt4, CPAD, hs4h, nullptr, nullptr, nullptr);
    agg40_lsm_kernel<<<a40Blocks, TB>>>(b4, out);
}

// round 17
// speedup vs baseline: 1.1538x; 1.0280x over previous
#include <cuda_runtime.h>
#include <cuda_bf16.h>
#include <cuda_fp16.h>
#include <cstdint>
#include <cstddef>

#define NNODES 50000
#define NEDGES 1600000
#define FIN    128
#define HID    256
#define NCLS   40
#define CPAD   64
#define NB_SCAN 49   // ceil(50000/1024)

// ================= static device scratch =================
__device__ float g_is[NNODES];
__device__ int   g_cnt[NNODES];     // zeroed by agg40_lsm tail each launch (zero-init at load)
__device__ int   g_rowptr[NNODES + 1];
__device__ int   g_srcs[NEDGES];
__device__ int   g_epos[NEDGES];    // per-edge slot within its dst bucket (from degree pass)
__device__ int   g_bsum[NB_SCAN];

__device__ uint8_t g_x8[(size_t)NNODES * FIN];    // is[n]*x[n] fp8 (layer-1 gather)
__device__ uint8_t g_a8[(size_t)NNODES * HID];    // fp8 activations (GEMM2/GEMM3 input)
__device__ uint8_t g_hs8[(size_t)NNODES * HID];   // layers 2/3 gather table fp8
__device__ __half  g_hs4h[(size_t)NNODES * CPAD]; // layer-4 gather table fp16 (precision!)

__device__ __nv_bfloat16 g_t[(size_t)NNODES * FIN];    // layer-1 GEMM input (bf16)
__device__ __nv_bfloat16 g_h0[(size_t)NNODES * HID];   // layer-4 GEMM input (bf16)

// weights transposed: Wt[n][k]
__device__ __nv_bfloat16 g_wt1[HID * FIN];   // bf16
__device__ uint8_t       g_w2f8[HID * HID];  // fp8
__device__ uint8_t       g_w3f8[HID * HID];  // fp8
__device__ __nv_bfloat16 g_wt4[CPAD * HID];  // bf16

#define W1E (FIN * HID)      // 32768 bf16 elems
#define W4E (HID * CPAD)     // 16384 bf16 elems
#define W2P (HID * HID / 2)  // 32768 fp8 pairs
#define W3P (HID * HID / 2)  // 32768 fp8 pairs
#define WPREP_ITERS (W1E + W4E + W2P + W3P)   // 114688

// ================= PTX helpers (base compute_103-legal only) =================
__device__ __forceinline__ uint32_t smem_u32(const void* p) {
    uint32_t a;
    asm("{ .reg .u64 t; cvta.to.shared.u64 t, %1; cvt.u32.u64 %0, t; }" : "=r"(a) : "l"(p));
    return a;
}
__device__ __forceinline__ void ldsm_x4(uint32_t& r0, uint32_t& r1, uint32_t& r2, uint32_t& r3,
                                        uint32_t addr) {
    asm volatile("ldmatrix.sync.aligned.m8n8.x4.shared.b16 {%0,%1,%2,%3}, [%4];"
                 : "=r"(r0), "=r"(r1), "=r"(r2), "=r"(r3) : "r"(addr));
}
__device__ __forceinline__ void mma16816(float& c0, float& c1, float& c2, float& c3,
                                         uint32_t a0, uint32_t a1, uint32_t a2, uint32_t a3,
                                         uint32_t b0, uint32_t b1) {
    asm volatile("mma.sync.aligned.m16n8k16.row.col.f32.bf16.bf16.f32 "
                 "{%0,%1,%2,%3}, {%4,%5,%6,%7}, {%8,%9}, {%0,%1,%2,%3};"
                 : "+f"(c0), "+f"(c1), "+f"(c2), "+f"(c3)
                 : "r"(a0), "r"(a1), "r"(a2), "r"(a3), "r"(b0), "r"(b1));
}
// fp8 mma: k32 e4m3, fragments byte-compatible with bf16-k16 ldmatrix loads
__device__ __forceinline__ void mma16832f8(float& c0, float& c1, float& c2, float& c3,
                                           uint32_t a0, uint32_t a1, uint32_t a2, uint32_t a3,
                                           uint32_t b0, uint32_t b1) {
    asm volatile("mma.sync.aligned.m16n8k32.row.col.f32.e4m3.e4m3.f32 "
                 "{%0,%1,%2,%3}, {%4,%5,%6,%7}, {%8,%9}, {%0,%1,%2,%3};"
                 : "+f"(c0), "+f"(c1), "+f"(c2), "+f"(c3)
                 : "r"(a0), "r"(a1), "r"(a2), "r"(a3), "r"(b0), "r"(b1));
}
__device__ __forceinline__ void cp_async16(uint32_t dst, const void* src, int sz) {
    asm volatile("cp.async.cg.shared.global [%0], [%1], 16, %2;"
                 :: "r"(dst), "l"(src), "r"(sz));
}
#define CP_COMMIT() asm volatile("cp.async.commit_group;")

__device__ __forceinline__ uint16_t f32x2_to_e4m3x2(float v0, float v1) {
    uint16_t q;
    asm("cvt.rn.satfinite.e4m3x2.f32 %0, %1, %2;" : "=h"(q) : "f"(v1), "f"(v0));
    return q;
}
__device__ __forceinline__ __half2 e4m3x2_to_h2(uint16_t q) {
    uint32_t h;
    asm("cvt.rn.f16x2.e4m3x2 %0, %1;" : "=r"(h) : "h"(q));
    return *reinterpret_cast<__half2*>(&h);
}
__device__ __forceinline__ void acch2_4(__half2* a, uint32_t v) {
    a[0] = __hadd2(a[0], e4m3x2_to_h2((uint16_t)(v & 0xFFFFu)));
    a[1] = __hadd2(a[1], e4m3x2_to_h2((uint16_t)(v >> 16)));
}
__device__ __forceinline__ void acch2_8(__half2* a, uint2 v) {
    acch2_4(a, v.x);
    acch2_4(a + 2, v.y);
}
__device__ __forceinline__ void acc4h(float* a, uint2 v) {
    __half2* h = reinterpret_cast<__half2*>(&v);
#pragma unroll
    for (int i = 0; i < 2; i++) {
        float2 f = __half22float2(h[i]);
        a[2 * i]     += f.x;
        a[2 * i + 1] += f.y;
    }
}

// ================= graph preprocessing =================
// degree + record each edge's slot in its dst bucket (de-atomizes fill)
__global__ void degree_kernel(const int* __restrict__ dst) {
    int e = blockIdx.x * blockDim.x + threadIdx.x;
    if (e < NEDGES) g_epos[e] = atomicAdd(&g_cnt[dst[e]], 1);
}
// block-local scan of degrees + g_is + x->fp8 prep + weight prep (fused)
__global__ __launch_bounds__(1024) void scan_block_kernel(
    const float4* __restrict__ x,
    const float* __restrict__ W1, const float* __restrict__ W2,
    const float* __restrict__ W3, const float* __restrict__ W4) {
    __shared__ int ws[32];
    __shared__ float sis[1024];
    int t = threadIdx.x, b = blockIdx.x;
    int i = b * 1024 + t;
    int v = (i < NNODES) ? g_cnt[i] : 0;
    float isn = rsqrtf((float)v + 1.0f);
    if (i < NNODES) g_is[i] = isn;
    sis[t] = isn;
    int lane = t & 31, w = t >> 5;
    int x_ = v;
#pragma unroll
    for (int off = 1; off < 32; off <<= 1) {
        int y = __shfl_up_sync(0xffffffffu, x_, off);
        if (lane >= off) x_ += y;
    }
    if (lane == 31) ws[w] = x_;
    __syncthreads();
    if (w == 0) {
        int s = ws[lane];
#pragma unroll
        for (int off = 1; off < 32; off <<= 1) {
            int y = __shfl_up_sync(0xffffffffu, s, off);
            if (lane >= off) s += y;
        }
        ws[lane] = s;
    }
    __syncthreads();
    int incl = x_ + (w ? ws[w - 1] : 0);
    if (i < NNODES) g_rowptr[i] = incl - v;
    if (t == 1023) g_bsum[b] = incl;

    // --- fused xprep ---
    int base_f4 = b * 32768;
#pragma unroll
    for (int it = 0; it < 32; it++) {
        int li = it * 1024 + t;
        int gf4 = base_f4 + li;
        if (gf4 < NNODES * 32) {
            float s = sis[li >> 5];
            float4 vv = x[gf4];
            uint16_t lo = f32x2_to_e4m3x2(s * vv.x, s * vv.y);
            uint16_t hi = f32x2_to_e4m3x2(s * vv.z, s * vv.w);
            reinterpret_cast<uint32_t*>(g_x8)[gf4] = (uint32_t)lo | ((uint32_t)hi << 16);
        }
    }
    // --- fused wprep: W1,W4 -> bf16 elems; W2,W3 -> fp8 pairs ---
    for (int j = b * 1024 + t; j < WPREP_ITERS; j += NB_SCAN * 1024) {
        if (j < W1E) {
            int n = j / FIN, k = j % FIN;
            g_wt1[j] = __float2bfloat16(W1[k * HID + n]);
        } else if (j < W1E + W4E) {
            int jj = j - W1E;
            int n = jj / HID, k = jj % HID;
            g_wt4[jj] = __float2bfloat16((n < NCLS) ? W4[k * NCLS + n] : 0.0f);
        } else if (j < W1E + W4E + W2P) {
            int p = j - W1E - W4E;              // pair idx: n = p/(HID/2), k0 = 2*(p%(HID/2))
            int n = p / (HID / 2), k0 = 2 * (p % (HID / 2));
            uint16_t q = f32x2_to_e4m3x2(W2[k0 * HID + n], W2[(k0 + 1) * HID + n]);
            reinterpret_cast<uint16_t*>(g_w2f8)[p] = q;
        } else {
            int p = j - W1E - W4E - W2P;
            int n = p / (HID / 2), k0 = 2 * (p % (HID / 2));
            uint16_t q = f32x2_to_e4m3x2(W3[k0 * HID + n], W3[(k0 + 1) * HID + n]);
            reinterpret_cast<uint16_t*>(g_w3f8)[p] = q;
        }
    }
}
// merged: scan block sums + apply offsets
__global__ __launch_bounds__(1024) void scan_finish_kernel() {
    __shared__ int s[64];
    int t = threadIdx.x, b = blockIdx.x;
    if (t < 64) s[t] = (t < NB_SCAN) ? g_bsum[t] : 0;
    __syncthreads();
    for (int off = 1; off < 64; off <<= 1) {
        int y = (t < 64 && t >= off) ? s[t - off] : 0;
        __syncthreads();
        if (t < 64) s[t] += y;
        __syncthreads();
    }
    int boff = (b > 0) ? s[b - 1] : 0;
    int i = b * 1024 + t;
    if (i < NNODES) g_rowptr[i] += boff;
    if (b == NB_SCAN - 1 && t == 0) g_rowptr[NNODES] = s[NB_SCAN - 1];
}
// atomic-free fill: slot precomputed by degree pass
__global__ void fill_kernel(const int* __restrict__ src, const int* __restrict__ dst) {
    int e = blockIdx.x * blockDim.x + threadIdx.x;
    if (e < NEDGES) g_srcs[g_rowptr[dst[e]] + g_epos[e]] = src[e];
}

// ================= aggregation kernels (fp8 gather, fp16 HADD2 accum) =================
// layer-1: warp per node; t[n] = is[n]*(sum_src x8[src] + x8[n]) -> bf16
__global__ __launch_bounds__(256) void agg_x_kernel() {
    int n = blockIdx.x * 8 + (threadIdx.x >> 5);
    int t = threadIdx.x & 31;
    if (n >= NNODES) return;
    const uint32_t* xr = reinterpret_cast<const uint32_t*>(g_x8);
    int beg = g_rowptr[n], end = g_rowptr[n + 1];
    __half2 a[2] = { __half2half2(__ushort_as_half(0)), __half2half2(__ushort_as_half(0)) };
    acch2_4(a, xr[(size_t)n * 32 + t]);
    int e = beg;
    for (; e + 4 <= end; e += 4) {
        int s0 = g_srcs[e], s1 = g_srcs[e + 1], s2 = g_srcs[e + 2], s3 = g_srcs[e + 3];
        uint32_t u0 = xr[(size_t)s0 * 32 + t];
        uint32_t u1 = xr[(size_t)s1 * 32 + t];
        uint32_t u2 = xr[(size_t)s2 * 32 + t];
        uint32_t u3 = xr[(size_t)s3 * 32 + t];
        acch2_4(a, u0); acch2_4(a, u1); acch2_4(a, u2); acch2_4(a, u3);
    }
    for (; e < end; e++) acch2_4(a, xr[(size_t)g_srcs[e] * 32 + t]);
    float isn = g_is[n];
    float2 f0 = __half22float2(a[0]);
    float2 f1 = __half22float2(a[1]);
    float vv[4] = { isn * f0.x, isn * f0.y, isn * f1.x, isn * f1.y };
    unsigned short hh[4];
#pragma unroll
    for (int k = 0; k < 4; k++) {
        __nv_bfloat16 h = __float2bfloat16(vv[k]);
        hh[k] = *reinterpret_cast<unsigned short*>(&h);
    }
    *(uint2*)(g_t + (size_t)n * FIN + 4 * t) = *(uint2*)hh;
}
// mid layers: warp per node, fp8 gather, fp16 HADD2 accum.
// OUT8=true -> fp8 out (GEMM3 input); false -> bf16 out (GEMM4 input).
template <bool OUT8>
__global__ __launch_bounds__(256) void agg_mid_kernel(
    const float* __restrict__ bias, uint8_t* __restrict__ o8,
    __nv_bfloat16* __restrict__ ob) {
    int n = blockIdx.x * 8 + (threadIdx.x >> 5);
    int t = threadIdx.x & 31;                // feats [8t, 8t+8)
    if (n >= NNODES) return;
    const uint2* hr = reinterpret_cast<const uint2*>(g_hs8);
    int beg = g_rowptr[n], end = g_rowptr[n + 1];
    __half2 a[4];
#pragma unroll
    for (int k = 0; k < 4; k++) a[k] = __half2half2(__ushort_as_half(0));
    acch2_8(a, hr[(size_t)n * 32 + t]);
    int e = beg;
    for (; e + 4 <= end; e += 4) {
        int s0 = g_srcs[e], s1 = g_srcs[e + 1], s2 = g_srcs[e + 2], s3 = g_srcs[e + 3];
        uint2 u0 = hr[(size_t)s0 * 32 + t];
        uint2 u1 = hr[(size_t)s1 * 32 + t];
        uint2 u2 = hr[(size_t)s2 * 32 + t];
        uint2 u3 = hr[(size_t)s3 * 32 + t];
        acch2_8(a, u0); acch2_8(a, u1); acch2_8(a, u2); acch2_8(a, u3);
    }
    for (; e < end; e++) acch2_8(a, hr[(size_t)g_srcs[e] * 32 + t]);
    float isn = g_is[n];
    float vv[8];
#pragma unroll
    for (int k = 0; k < 4; k++) {
        float2 f = __half22float2(a[k]);
        vv[2 * k]     = fmaxf(isn * f.x + bias[8 * t + 2 * k], 0.0f);
        vv[2 * k + 1] = fmaxf(isn * f.y + bias[8 * t + 2 * k + 1], 0.0f);
    }
    if (OUT8) {
        uint16_t q[4];
#pragma unroll
        for (int k = 0; k < 4; k++) q[k] = f32x2_to_e4m3x2(vv[2 * k], vv[2 * k + 1]);
        uint2 pk;
        pk.x = (uint32_t)q[0] | ((uint32_t)q[1] << 16);
        pk.y = (uint32_t)q[2] | ((uint32_t)q[3] << 16);
        *(uint2*)(o8 + (size_t)n * HID + 8 * t) = pk;
    } else {
        unsigned short hh[8];
#pragma unroll
        for (int k = 0; k < 8; k++) {
            __nv_bfloat16 h = __float2bfloat16(vv[k]);
            hh[k] = *reinterpret_cast<unsigned short*>(&h);
        }
        *(uint4*)(ob + (size_t)n * HID + 8 * t) = *(uint4*)hh;
    }
}
// layer 4: fp16 gather + fp32 accum; + log_softmax; zeroes g_cnt for next launch
__global__ __launch_bounds__(256) void agg40_lsm_kernel(
    const float* __restrict__ b4, float* __restrict__ out) {
    int gi = blockIdx.x * blockDim.x + threadIdx.x;
    if (gi < NNODES) g_cnt[gi] = 0;
    int n = blockIdx.x * 16 + (threadIdx.x >> 4);
    int t = threadIdx.x & 15;
    if (n >= NNODES) return;
    const uint2* hr = reinterpret_cast<const uint2*>(g_hs4h);
    int beg = g_rowptr[n], end = g_rowptr[n + 1];
    float a[4] = {0.f, 0.f, 0.f, 0.f};
    acc4h(a, hr[(size_t)n * 16 + t]);
    int e = beg;
    for (; e + 4 <= end; e += 4) {
        int s0 = g_srcs[e], s1 = g_srcs[e + 1], s2 = g_srcs[e + 2], s3 = g_srcs[e + 3];
        uint2 u0 = hr[(size_t)s0 * 16 + t];
        uint2 u1 = hr[(size_t)s1 * 16 + t];
        uint2 u2 = hr[(size_t)s2 * 16 + t];
        uint2 u3 = hr[(size_t)s3 * 16 + t];
        acc4h(a, u0); acc4h(a, u1); acc4h(a, u2); acc4h(a, u3);
    }
    for (; e < end; e++) acc4h(a, hr[(size_t)g_srcs[e] * 16 + t]);
    float sc = g_is[n];
    int col0 = 4 * t;
    float v[4];
#pragma unroll
    for (int k = 0; k < 4; k++)
        v[k] = (col0 + k < NCLS) ? (sc * a[k] + b4[col0 + k]) : -1e30f;
    float m = fmaxf(fmaxf(v[0], v[1]), fmaxf(v[2], v[3]));
#pragma unroll
    for (int off = 8; off; off >>= 1) m = fmaxf(m, __shfl_xor_sync(0xffffffffu, m, off));
    float se = 0.f;
#pragma unroll
    for (int k = 0; k < 4; k++) se += (col0 + k < NCLS) ? __expf(v[k] - m) : 0.f;
#pragma unroll
    for (int off = 8; off; off >>= 1) se += __shfl_xor_sync(0xffffffffu, se, off);
    float lse = m + __logf(se);
    if (t < 10) {
        float4 o;
        o.x = v[0] - lse; o.y = v[1] - lse; o.z = v[2] - lse; o.w = v[3] - lse;
        *(float4*)(out + (size_t)n * NCLS + col0) = o;
    }
}

// ================= HMMA GEMM (bf16 or fp8), cp.async pipelined =================
// KTU: K extent in 16-bit units (bf16 elems, or fp8 PAIRS). Row byte stride = KTU*2.
// FP8E=true uses e4m3 k32 mma (fragments byte-compatible with bf16 ldmatrix loads).
// MODE 0: Ch = D*g_is[m] fp16; MODE 2: C8 = fp8(D*g_is[m]); MODE 3: relu(D+bias) -> fp8 C8.
#define ASTR 72

template <int KTU, int BN_T, int MODE, bool FP8E>
__global__ __launch_bounds__(256, 2) void mma_gemm_kernel(
    const void* __restrict__ Av, const void* __restrict__ Bv,
    int NT,
    __half* __restrict__ Ch,
    uint8_t* __restrict__ C8,
    const float* __restrict__ bias)
{
    extern __shared__ __nv_bfloat16 sm[];
    constexpr int NCH = KTU / 64;          // chunks of 64 b16-units (128 bytes)
    constexpr int BSTR = KTU + 8;          // smem row stride (b16 units)
    constexpr int ASTG_B = 128 * ASTR * 2;
    constexpr int ABUF_B = 2 * ASTG_B;
    const uint8_t* A = (const uint8_t*)Av;
    const uint8_t* B = (const uint8_t*)Bv;
    const size_t rowb = (size_t)KTU * 2;

    const int tid = threadIdx.x;
    const int lane = tid & 31;
    const int wid = tid >> 5;
    const int wm = wid & 3;
    const int wn = wid >> 2;
    constexpr int WN = BN_T / 2;
    constexpr int NTILES = WN / 8;

    const int row0 = blockIdx.x * 128;
    const int col0 = blockIdx.y * BN_T;

    const uint32_t uS = smem_u32(sm);
    const uint32_t uB = uS + ABUF_B;

    auto loadA = [&](int c) {
        uint32_t ab = uS + (c & 1) * ASTG_B;
#pragma unroll
        for (int it = 0; it < 4; it++) {
            int idx = tid + it * 256;
            int r = idx >> 3, q = idx & 7;
            int gr = row0 + r;
            int sz = (gr < NNODES) ? 16 : 0;
            cp_async16(ab + (uint32_t)(r * ASTR + q * 8) * 2,
                       A + (size_t)gr * rowb + c * 128 + q * 16, sz);
        }
    };

    {
        constexpr int BUNITS = BN_T * KTU / 8;   // 16B units
        for (int u = tid; u < BUNITS; u += 256) {
            int n = u / (KTU / 8), q = u % (KTU / 8);
            cp_async16(uB + (uint32_t)(n * BSTR + q * 8) * 2,
                       B + (size_t)(col0 + n) * rowb + q * 16, 16);
        }
        loadA(0);
        CP_COMMIT();
    }

    float acc[2][NTILES][4];
#pragma unroll
    for (int i = 0; i < 2; i++)
#pragma unroll
        for (int j = 0; j < NTILES; j++)
#pragma unroll
            for (int q = 0; q < 4; q++) acc[i][j][q] = 0.0f;

    const int a_r = (lane & 7) + ((lane >> 3) & 1) * 8;
    const int a_k = (lane >> 4) * 8;
    const int b_n = (lane & 7) + ((lane >> 4) & 1) * 8;
    const int b_k = ((lane >> 3) & 1) * 8;

#pragma unroll
    for (int c = 0; c < NCH; c++) {
        if (c + 1 < NCH) {
            loadA(c + 1);
            CP_COMMIT();
            asm volatile("cp.async.wait_group 1;");
        } else {
            asm volatile("cp.async.wait_group 0;");
        }
        __syncthreads();

        uint32_t ab = uS + (c & 1) * ASTG_B;
#pragma unroll
        for (int ks = 0; ks < 4; ks++) {
            uint32_t ah[2][4];
#pragma unroll
            for (int mt = 0; mt < 2; mt++) {
                uint32_t off = (uint32_t)(((wm * 32 + mt * 16 + a_r) * ASTR + ks * 16 + a_k) * 2);
                ldsm_x4(ah[mt][0], ah[mt][1], ah[mt][2], ah[mt][3], ab + off);
            }
            uint32_t bh[NTILES][2];
#pragma unroll
            for (int nb = 0; nb < NTILES / 2; nb++) {
                uint32_t off = (uint32_t)(((wn * WN + nb * 16 + b_n) * BSTR + c * 64 + ks * 16 + b_k) * 2);
                uint32_t r0, r1, r2, r3;
                ldsm_x4(r0, r1, r2, r3, uB + off);
                bh[nb * 2][0] = r0; bh[nb * 2][1] = r1;
                bh[nb * 2 + 1][0] = r2; bh[nb * 2 + 1][1] = r3;
            }
#pragma unroll
            for (int mt = 0; mt < 2; mt++)
#pragma unroll
                for (int nt = 0; nt < NTILES; nt++) {
                    if (FP8E)
                        mma16832f8(acc[mt][nt][0], acc[mt][nt][1], acc[mt][nt][2], acc[mt][nt][3],
                                   ah[mt][0], ah[mt][1], ah[mt][2], ah[mt][3], bh[nt][0], bh[nt][1]);
                    else
                        mma16816(acc[mt][nt][0], acc[mt][nt][1], acc[mt][nt][2], acc[mt][nt][3],
                                 ah[mt][0], ah[mt][1], ah[mt][2], ah[mt][3], bh[nt][0], bh[nt][1]);
                }
        }
        __syncthreads();
    }

    // ---- epilogue ----
    const int rbase = row0 + wm * 32 + (lane >> 2);
    const int cbase = col0 + wn * WN + ((lane & 3) * 2);
#pragma unroll
    for (int mt = 0; mt < 2; mt++) {
#pragma unroll
        for (int half = 0; half < 2; half++) {
            int gr = rbase + mt * 16 + half * 8;
            if (gr < NNODES) {
                if (MODE == 0) {
                    float s = g_is[gr];
#pragma unroll
                    for (int nt = 0; nt < NTILES; nt++) {
                        __half2 p = __floats2half2_rn(acc[mt][nt][half * 2 + 0] * s,
                                                      acc[mt][nt][half * 2 + 1] * s);
                        *(__half2*)(Ch + (size_t)gr * NT + cbase + nt * 8) = p;
                    }
                } else if (MODE == 2) {
                    float s = g_is[gr];
#pragma unroll
                    for (int nt = 0; nt < NTILES; nt++) {
                        uint16_t q = f32x2_to_e4m3x2(acc[mt][nt][half * 2 + 0] * s,
                                                     acc[mt][nt][half * 2 + 1] * s);
                        *(uint16_t*)(C8 + (size_t)gr * NT + cbase + nt * 8) = q;
                    }
                } else {  // MODE 3: relu(D + bias) -> fp8
#pragma unroll
                    for (int nt = 0; nt < NTILES; nt++) {
                        int c = cbase + nt * 8;
                        float v0 = fmaxf(acc[mt][nt][half * 2 + 0] + bias[c], 0.0f);
                        float v1 = fmaxf(acc[mt][nt][half * 2 + 1] + bias[c + 1], 0.0f);
                        *(uint16_t*)(C8 + (size_t)gr * NT + c) = f32x2_to_e4m3x2(v0, v1);
                    }
                }
            }
        }
    }
}

// ================= launch =================
extern "C" void kernel_launch(void* const* d_in, const int* in_sizes, int n_in,
                              void* d_out, int out_size)
{
    const float* x  = (const float*)d_in[0];
    const int*   ei = (const int*)  d_in[1];
    const float* W1 = (const float*)d_in[2];
    const float* b1 = (const float*)d_in[3];
    const float* W2 = (const float*)d_in[4];
    const float* b2 = (const float*)d_in[5];
    const float* W3 = (const float*)d_in[6];
    const float* b3 = (const float*)d_in[7];
    const float* W4 = (const float*)d_in[8];
    const float* b4 = (const float*)d_in[9];
    float* out = (float*)d_out;

    const int* src = ei;
    const int* dst = ei + NEDGES;

    __nv_bfloat16 *tptr, *h0, *wt1, *wt4;
    __half* hs4h;
    uint8_t *a8, *hs8, *w2f8, *w3f8;
    cudaGetSymbolAddress((void**)&tptr, g_t);
    cudaGetSymbolAddress((void**)&h0,  g_h0);
    cudaGetSymbolAddress((void**)&wt1, g_wt1);
    cudaGetSymbolAddress((void**)&wt4, g_wt4);
    cudaGetSymbolAddress((void**)&a8,   g_a8);
    cudaGetSymbolAddress((void**)&hs8,  g_hs8);
    cudaGetSymbolAddress((void**)&w2f8, g_w2f8);
    cudaGetSymbolAddress((void**)&w3f8, g_w3f8);
    cudaGetSymbolAddress((void**)&hs4h, g_hs4h);

    // smem: A 2-stage 36864B + B resident BN*(KTU+8)*2B
    const int SMEM_K128 = 36864 + 128 * (128 + 8) * 2;  // 71680 (gemm1 bf16 K128, gemm2/3 fp8 K256)
    const int SMEM_L4   = 36864 + 64  * (256 + 8) * 2;  // 70656
    cudaFuncSetAttribute(mma_gemm_kernel<128, 128, 3, false>, cudaFuncAttributeMaxDynamicSharedMemorySize, SMEM_K128);
    cudaFuncSetAttribute(mma_gemm_kernel<128, 128, 2, true>,  cudaFuncAttributeMaxDynamicSharedMemorySize, SMEM_K128);
    cudaFuncSetAttribute(mma_gemm_kernel<256, 64, 0, false>,  cudaFuncAttributeMaxDynamicSharedMemorySize, SMEM_L4);

    const int TB = 256;
    int edgeBlocks = (NEDGES + TB - 1) / TB;

    // ---- graph build + fused preps ----
    degree_kernel<<<edgeBlocks, TB>>>(dst);
    scan_block_kernel<<<NB_SCAN, 1024>>>((const float4*)x, W1, W2, W3, W4);
    scan_finish_kernel<<<NB_SCAN, 1024>>>();
    fill_kernel<<<edgeBlocks, TB>>>(src, dst);

    int mBlocks = (NNODES + 127) / 128;          // 391
    dim3 gHID(mBlocks, 2);
    dim3 gC(mBlocks, 1);
    int warpNodeBlocks = (NNODES + 7) / 8;       // 6250
    int a40Blocks = (NNODES + 15) / 16;          // 3125

    // layer 1: aggregate-first, bf16 GEMM, epilogue relu+bias -> fp8 (GEMM2 input)
    agg_x_kernel<<<warpNodeBlocks, TB>>>();
    mma_gemm_kernel<128, 128, 3, false><<<gHID, 256, SMEM_K128>>>(
        tptr, wt1, HID, nullptr, a8, b1);
    // layer 2: fp8 GEMM -> fp8 table; agg -> fp8 (GEMM3 input)
    mma_gemm_kernel<128, 128, 2, true><<<gHID, 256, SMEM_K128>>>(
        a8, w2f8, HID, nullptr, hs8, nullptr);
    agg_mid_kernel<true><<<warpNodeBlocks, TB>>>(b2, a8, nullptr);
    // layer 3: fp8 GEMM -> fp8 table; agg -> bf16 (GEMM4 input)
    mma_gemm_kernel<128, 128, 2, true><<<gHID, 256, SMEM_K128>>>(
        a8, w3f8, HID, nullptr, hs8, nullptr);
    agg_mid_kernel<false><<<warpNodeBlocks, TB>>>(b3, nullptr, h0);
    // layer 4: bf16 GEMM (precision-critical) + log_softmax
    mma_gemm_kernel<256, 64, 0, false><<<gC, 256, SMEM_L4>>>(
        h0, wt4, CPAD, hs4h, nullptr, nullptr);
    agg40_lsm_kernel<<<a40Blocks, TB>>>(b4, out);
}